// round 7
// baseline (speedup 1.0000x reference)
#include <cuda_runtime.h>

// Problem constants
constexpr int B_ = 8, L_ = 12, C_ = 4096, O_ = 128, N_ = 4224;
constexpr int E_ = 64, A_ = 64, H_ = 256;
constexpr int DCOLS = 80;  // X cols: 0..63 tIn, 64..75 proj_s, 76 = ones, 77..79 pad

// ---------------- scratch (device globals) ----------------------------------
__device__ __align__(16) float g_objIn[B_ * O_ * E_];
__device__ __align__(16) float g_objOut[B_ * O_ * E_];
__device__ __align__(16) float g_T1c[C_ * H_];
__device__ __align__(16) float g_T1o[B_ * O_ * H_];
__device__ __align__(16) float g_meta[B_ * L_ * A_];
__device__ __align__(16) float g_u[B_ * L_ * H_];
__device__ __align__(16) float g_arg[B_ * L_ * E_];
__device__ __align__(16) float g_parg[B_ * L_ * H_];
__device__ __align__(16) float g_proj[B_ * N_ * 16];
__device__ __align__(16) float g_psum[B_ * 16];
__device__ __align__(16) float g_tInsum[B_ * E_];
__device__ __align__(16) float g_D[B_ * L_ * H_ * DCOLS];   // [bt][h][c]
__device__ __align__(16) float g_E[B_ * L_ * DCOLS * 64];   // [bt][c][e'] (transposed)
__device__ __align__(16) float g_Msum[B_ * E_ * A_];
__device__ __align__(16) float g_ol[B_ * N_];
__device__ int g_olmax[B_];

__device__ __forceinline__ unsigned long long pack2(float v) {
    unsigned int b = __float_as_uint(v);
    return ((unsigned long long)b << 32) | b;
}
__device__ __forceinline__ float lo2(unsigned long long v) {
    return __uint_as_float((unsigned)(v & 0xffffffffULL));
}
__device__ __forceinline__ float hi2(unsigned long long v) {
    return __uint_as_float((unsigned)(v >> 32));
}

// ---------------- zero accumulators -----------------------------------------
__global__ void k_zero() {
    int i = blockIdx.x * 256 + threadIdx.x;
    float4 z = make_float4(0.f, 0.f, 0.f, 0.f);
    if (i < B_ * L_ * H_ * DCOLS / 4) ((float4*)g_D)[i] = z;
    if (i < B_ * 16) g_psum[i] = 0.f;
    if (i < B_ * E_) g_tInsum[i] = 0.f;
    if (i < B_) g_olmax[i] = 0;
}

// ---------------- fused obj + T1o (16 objects per block) ----------------------
__global__ void __launch_bounds__(256) k_objT1o(
    const float* __restrict__ clsIn, const float* __restrict__ clsOut,
    const float* __restrict__ atIn, const float* __restrict__ atOut,
    const int* __restrict__ gt_cls, const int* __restrict__ gt_attr,
    const float* __restrict__ w1) {
    int tid = threadIdx.x;
    int b = blockIdx.y;
    int o0 = blockIdx.x * 16;
    __shared__ float s_out[1024];   // 16 objOut rows
    __shared__ float s_w[4096];     // 16 e-rows x 256 h
    for (int i = tid; i < 1024; i += 256) {
        int r = i >> 6, e = i & 63;
        int o = o0 + r;
        int cls = gt_cls[b * O_ + o];
        float vi = clsIn[cls * E_ + e];
        float vo = clsOut[cls * E_ + e];
#pragma unroll
        for (int k = 0; k < 8; k++) {
            int at = gt_attr[(b * O_ + o) * 8 + k];
            vi += atIn[at * E_ + e];
            vo += atOut[at * E_ + e];
        }
        g_objIn[(b * O_ + o) * E_ + e] = vi;
        g_objOut[(b * O_ + o) * E_ + e] = vo;
        s_out[i] = vo;
    }
    int h = tid;
    float acc[16];
#pragma unroll
    for (int r = 0; r < 16; r++) acc[r] = 0.f;
    for (int ch = 0; ch < 4; ch++) {
        __syncthreads();
        {
            const float4* src = (const float4*)(w1 + ch * 16 * H_);
            float4* dst = (float4*)s_w;
            for (int i = tid; i < 1024; i += 256) dst[i] = src[i];
        }
        __syncthreads();
#pragma unroll
        for (int e = 0; e < 16; e++) {
            float w = s_w[e * H_ + h];
            int ge = ch * 16 + e;
#pragma unroll
            for (int r = 0; r < 16; r++) acc[r] += s_out[r * 64 + ge] * w;
        }
    }
#pragma unroll
    for (int r = 0; r < 16; r++) g_T1o[(b * O_ + o0 + r) * H_ + h] = acc[r];
}

// T1c[n,h] = concept_embOut[n,:] @ axon_w1[0:64,:]  (16 rows per block)
__global__ void __launch_bounds__(256) k_T1c(const float* __restrict__ cOut,
                                             const float* __restrict__ w1) {
    int h = threadIdx.x;
    int n0 = blockIdx.x * 16;
    __shared__ float s_emb[1024];
    __shared__ float s_w[4096];
    for (int i = h; i < 1024; i += 256) s_emb[i] = cOut[n0 * E_ + i];
    float acc[16];
#pragma unroll
    for (int r = 0; r < 16; r++) acc[r] = 0.f;
    for (int ch = 0; ch < 4; ch++) {
        __syncthreads();
        {
            const float4* src = (const float4*)(w1 + ch * 16 * H_);
            float4* dst = (float4*)s_w;
            for (int i = h; i < 1024; i += 256) dst[i] = src[i];
        }
        __syncthreads();
#pragma unroll
        for (int e = 0; e < 16; e++) {
            float w = s_w[e * H_ + h];
            int ge = ch * 16 + e;
#pragma unroll
            for (int r = 0; r < 16; r++) acc[r] += s_emb[r * 64 + ge] * w;
        }
    }
#pragma unroll
    for (int r = 0; r < 16; r++) g_T1c[(n0 + r) * H_ + h] = acc[r];
}

// fused arg gather + parg
__global__ void __launch_bounds__(256) k_argparg(
    const float* __restrict__ cOut, const int* __restrict__ args,
    const float* __restrict__ mw1, const float* __restrict__ mb1) {
    int bt = blockIdx.x;
    int h = threadIdx.x;
    __shared__ float s_a[64];
    if (h < 64) {
        int ai = args[bt];
        float v = cOut[ai * E_ + h];
        s_a[h] = v;
        g_arg[bt * E_ + h] = v;
    }
    __syncthreads();
    float p = mb1[h];
#pragma unroll
    for (int e = 0; e < 64; e++) p += s_a[e] * __ldg(&mw1[(64 + e) * H_ + h]);
    g_parg[bt * H_ + h] = p;
}

__global__ void __launch_bounds__(256) k_meta(
    const float* __restrict__ meta_init,
    const float* __restrict__ mw1, const float* __restrict__ mw2,
    const float* __restrict__ mb2, const int* __restrict__ ops) {
    extern __shared__ float dsm[];
    float* s_w1a = dsm;            // 64*256
    float* s_w2m = dsm + 16384;    // 256*64
    __shared__ float s_meta[64], s_h[256], s_part[256];
    int b = blockIdx.x;
    int tid = threadIdx.x;
    {
        const float4* w1_4 = (const float4*)mw1;
        float4* d1 = (float4*)s_w1a;
        for (int i = tid; i < 4096; i += 256) d1[i] = w1_4[i];
        const float4* w2_4 = (const float4*)mw2;
        float4* d2 = (float4*)s_w2m;
        for (int i = tid; i < 4096; i += 256) d2[i] = w2_4[i];
    }
    float r_mb2 = (tid < 64) ? mb2[tid] : 0.f;
    if (tid < 64) s_meta[tid] = meta_init[tid];
    __syncthreads();
    for (int t = 0; t < L_; t++) {
        float pre = g_parg[(b * L_ + t) * H_ + tid];
#pragma unroll
        for (int a = 0; a < 64; a++) pre += s_meta[a] * s_w1a[a * H_ + tid];
        s_h[tid] = fmaxf(pre, 0.f);
        __syncthreads();
        {
            int a = tid & 63;
            int base = (tid >> 6) * 64;
            float s = 0.f;
#pragma unroll
            for (int hh = 0; hh < 64; hh++)
                s += s_h[base + hh] * s_w2m[(base + hh) * A_ + a];
            s_part[tid] = s;
        }
        __syncthreads();
        if (tid < 64) {
            float nm = r_mb2 + s_part[tid] + s_part[64 + tid] +
                       s_part[128 + tid] + s_part[192 + tid];
            float nv = (ops[b * L_ + t] == 0) ? nm : s_meta[tid];
            s_meta[tid] = nv;
            g_meta[(b * L_ + t) * A_ + tid] = nv;
        }
        __syncthreads();
    }
}

__global__ void __launch_bounds__(256) k_u(const float* __restrict__ aw1,
                                           const float* __restrict__ ab1) {
    int bt = blockIdx.x;
    int tid = threadIdx.x;
    __shared__ float s_m[64];
    if (tid < 64) s_m[tid] = g_meta[bt * A_ + tid];
    __syncthreads();
    float uv = ab1[tid];
#pragma unroll
    for (int a = 0; a < 64; a++) uv += s_m[a] * __ldg(&aw1[(64 + a) * H_ + tid]);
    g_u[bt * H_ + tid] = uv;
}

__global__ void __launch_bounds__(256) k_proj(const float* __restrict__ cOut) {
    int b = blockIdx.y;
    int tid = threadIdx.x;
    int w = tid >> 5, lane = tid & 31;
    __shared__ float s_arg[768];
    __shared__ float s_p[8][16];
    for (int i = tid; i < 768; i += 256) s_arg[i] = g_arg[b * 768 + i];
    __syncthreads();
    int n = blockIdx.x * 8 + w;
    const float* row = (n < C_) ? cOut + (size_t)n * 64
                                : g_objOut + (size_t)(b * O_ + n - C_) * 64;
    float x0 = row[lane], x1 = row[lane + 32];
#pragma unroll
    for (int s = 0; s < 12; s++) {
        float p = x0 * s_arg[s * 64 + lane] + x1 * s_arg[s * 64 + 32 + lane];
#pragma unroll
        for (int o = 16; o > 0; o >>= 1) p += __shfl_xor_sync(0xffffffffu, p, o);
        if (lane == 0) s_p[w][s] = p * (1.0f / 64.0f);
    }
    __syncwarp();
    if (lane < 16) {
        float v = (lane < 12) ? s_p[w][lane] : ((lane == 12) ? 1.0f : 0.0f);
        g_proj[(size_t)(b * N_ + n) * 16 + lane] = v;
        if (lane < 12) atomicAdd(&g_psum[b * 16 + lane], v);
    }
}

__global__ void __launch_bounds__(64) k_tinsum(const float* __restrict__ cIn) {
    int b = blockIdx.y;
    int e = threadIdx.x;
    int n0 = blockIdx.x * 64;
    float s = 0.f;
    for (int r = 0; r < 64; r++) {
        int n = n0 + r;
        const float* row = (n < C_) ? cIn + (size_t)n * 64
                                    : g_objIn + (size_t)(b * O_ + n - C_) * 64;
        s += row[e];
    }
    atomicAdd(&g_tInsum[b * E_ + e], s);
}

// ---------------- big GEMM: D_t = Hrel_t^T @ [tIn | proj | 1] ----------------
// 512 threads: (h = tid&255, cq = tid>>8); each thread owns 40 of 80 D-columns.
__global__ void __launch_bounds__(512, 2) k_D(const int* __restrict__ ops,
                                              const float* __restrict__ cIn) {
    int t = blockIdx.y, b = blockIdx.z;
    if (ops[b * L_ + t] != 2) return;
    int tid = threadIdx.x;
    int h = tid & 255, cq = tid >> 8;
    __shared__ __align__(16) float s_X[64 * 80];
    float uh = g_u[(b * L_ + t) * H_ + h];
    unsigned long long acc[20];
#pragma unroll
    for (int j = 0; j < 20; j++) acc[j] = 0ULL;
    int nbase = blockIdx.x * 192;
    for (int tile = 0; tile < 3; tile++) {
        int n0 = nbase + tile * 64;
        {
            float4* dst = (float4*)s_X;
            for (int i = tid; i < 1024; i += 512) {
                int r = i >> 4, c = i & 15;
                int n = n0 + r;
                const float4* src = (n < C_)
                    ? (const float4*)cIn + (size_t)n * 16
                    : (const float4*)g_objIn + (size_t)(b * O_ + n - C_) * 16;
                dst[r * 20 + c] = src[c];
            }
            if (tid < 256) {
                int r = tid >> 2, c = tid & 3;
                dst[r * 20 + 16 + c] =
                    ((const float4*)g_proj)[(size_t)(b * N_ + n0 + r) * 4 + c];
            }
        }
        __syncthreads();
        // depth-2 prefetch of T1 rows
        float t1a = (n0 < C_) ? g_T1c[n0 * H_ + h]
                              : g_T1o[(b * O_ + n0 - C_) * H_ + h];
        int n1 = n0 + 1;
        float t1b = (n1 < C_) ? g_T1c[n1 * H_ + h]
                              : g_T1o[(b * O_ + n1 - C_) * H_ + h];
        for (int nl = 0; nl < 64; nl++) {
            float hv = fmaxf(t1a + uh, 0.f);
            t1a = t1b;
            if (nl < 62) {
                int n = n0 + nl + 2;
                t1b = (n < C_) ? g_T1c[n * H_ + h]
                               : g_T1o[(b * O_ + n - C_) * H_ + h];
            }
            unsigned long long hv2 = pack2(hv);
            const ulonglong2* xr = (const ulonglong2*)(s_X + nl * 80) + cq * 10;
#pragma unroll
            for (int j = 0; j < 10; j++) {
                ulonglong2 p = xr[j];
                asm("fma.rn.f32x2 %0, %1, %2, %0;" : "+l"(acc[2 * j]) : "l"(hv2), "l"(p.x));
                asm("fma.rn.f32x2 %0, %1, %2, %0;" : "+l"(acc[2 * j + 1]) : "l"(hv2), "l"(p.y));
            }
        }
        __syncthreads();
    }
    float* dp = g_D + ((size_t)(b * L_ + t) * H_ + h) * DCOLS + cq * 40;
#pragma unroll
    for (int j = 0; j < 20; j++) {
        asm volatile("red.global.add.v2.f32 [%0], {%1, %2};"
                     :: "l"(dp + 2 * j), "f"(lo2(acc[j])), "f"(hi2(acc[j])) : "memory");
    }
}

// ---------------- k_E: E_t = W2^T @ D_t  (stored transposed [c][e']) ----------
__global__ void __launch_bounds__(256) k_E(const int* __restrict__ ops,
                                           const float* __restrict__ w2) {
    int t = blockIdx.x, b = blockIdx.y;
    if (ops[b * L_ + t] != 2) return;
    int tid = threadIdx.x;
    int ep = tid & 63;   // e'
    int cq = tid >> 6;   // 0..3, each 20 cols
    __shared__ __align__(16) float s_D[64 * 80];   // [hh][c]
    __shared__ __align__(16) float s_w2[64 * 64];  // [hh][e']
    unsigned long long acc[10];
#pragma unroll
    for (int j = 0; j < 10; j++) acc[j] = 0ULL;
    size_t dbase = (size_t)(b * L_ + t) * H_ * DCOLS;
    for (int ch = 0; ch < 4; ch++) {
        __syncthreads();
        {
            const float4* src = (const float4*)(g_D + dbase + ch * 64 * DCOLS);
            float4* dst = (float4*)s_D;
            for (int i = tid; i < 1280; i += 256) dst[i] = src[i];
            const float4* wsrc = (const float4*)(w2 + ch * 64 * 64);
            float4* wdst = (float4*)s_w2;
            for (int i = tid; i < 1024; i += 256) wdst[i] = wsrc[i];
        }
        __syncthreads();
        const unsigned long long* D2 = (const unsigned long long*)s_D;
#pragma unroll 8
        for (int hh = 0; hh < 64; hh++) {
            unsigned long long w2v = pack2(s_w2[hh * 64 + ep]);
            const unsigned long long* drow = D2 + hh * 40 + cq * 10;
#pragma unroll
            for (int j = 0; j < 10; j++) {
                asm("fma.rn.f32x2 %0, %1, %2, %0;" : "+l"(acc[j]) : "l"(w2v), "l"(drow[j]));
            }
        }
    }
    float* eb = g_E + (size_t)(b * L_ + t) * DCOLS * 64;
#pragma unroll
    for (int j = 0; j < 10; j++) {
        int c = cq * 20 + 2 * j;
        eb[c * 64 + ep] = lo2(acc[j]);
        eb[(c + 1) * 64 + ep] = hi2(acc[j]);
    }
}

// ---------------- tiny serial recurrence: Msum, attsum ------------------------
__global__ void __launch_bounds__(1024) k_rec(const int* __restrict__ ops,
                                              const float* __restrict__ b2,
                                              const float* __restrict__ att_init) {
    __shared__ __align__(16) float s_Ms[4096];   // [e][a]
    __shared__ __align__(16) float s_E[5120];    // [c][e']
    __shared__ float s_meta[768], s_tmp[1024];
    __shared__ float s_as[64], s_ai[64], s_tis[64], s_b2[64], s_ps[12];
    __shared__ int s_op[12];
    int b = blockIdx.x, tid = threadIdx.x;
    for (int i = tid; i < 4096; i += 1024) s_Ms[i] = 0.f;
    if (tid < 768) s_meta[tid] = g_meta[b * 768 + tid];
    if (tid < 64) {
        s_ai[tid] = att_init[tid];
        s_as[tid] = (float)N_ * att_init[tid];
        s_tis[tid] = g_tInsum[b * 64 + tid];
        s_b2[tid] = b2[tid];
    }
    if (tid < 12) { s_op[tid] = ops[b * L_ + tid]; s_ps[tid] = g_psum[b * 16 + tid]; }
    __syncthreads();
    const float invN = 1.0f / (float)N_;
    int a = tid & 63, eg = tid >> 6;
    int e0 = eg * 4;
    for (int t = 0; t < L_; t++) {
        int op = s_op[t];
        if (op == 1) {
            if (tid < 64) s_as[tid] += s_ps[t] * s_meta[t * 64 + tid];
            __syncthreads();
        } else if (op == 2) {
            const float* esrc = g_E + (size_t)(b * L_ + t) * 5120;
            for (int i = tid; i < 5120; i += 1024) s_E[i] = esrc[i];
            __syncthreads();
            float aiv = s_ai[a];
            unsigned long long ai2 = pack2(aiv);
            unsigned long long acc2[2];
            {
                ulonglong2 es = *(const ulonglong2*)(s_E + 76 * 64 + e0);
                acc2[0] = 0ULL; acc2[1] = 0ULL;
                asm("fma.rn.f32x2 %0, %1, %2, %0;" : "+l"(acc2[0]) : "l"(es.x), "l"(ai2));
                asm("fma.rn.f32x2 %0, %1, %2, %0;" : "+l"(acc2[1]) : "l"(es.y), "l"(ai2));
            }
            for (int s = 0; s < t; s++)
                if (s_op[s] == 1) {
                    unsigned long long mv = pack2(s_meta[s * 64 + a]);
                    ulonglong2 er = *(const ulonglong2*)(s_E + (64 + s) * 64 + e0);
                    asm("fma.rn.f32x2 %0, %1, %2, %0;" : "+l"(acc2[0]) : "l"(er.x), "l"(mv));
                    asm("fma.rn.f32x2 %0, %1, %2, %0;" : "+l"(acc2[1]) : "l"(er.y), "l"(mv));
                }
#pragma unroll 8
            for (int e = 0; e < 64; e++) {
                unsigned long long ms = pack2(s_Ms[e * 64 + a]);
                ulonglong2 ek = *(const ulonglong2*)(s_E + e * 64 + e0);
                asm("fma.rn.f32x2 %0, %1, %2, %0;" : "+l"(acc2[0]) : "l"(ek.x), "l"(ms));
                asm("fma.rn.f32x2 %0, %1, %2, %0;" : "+l"(acc2[1]) : "l"(ek.y), "l"(ms));
            }
            float asv = s_as[a];
            float m[4] = {lo2(acc2[0]), hi2(acc2[0]), lo2(acc2[1]), hi2(acc2[1])};
            float part = 0.f;
#pragma unroll
            for (int j = 0; j < 4; j++) {
                m[j] = (m[j] + s_b2[e0 + j] * asv) * invN;
                part += s_tis[e0 + j] * m[j];
            }
            s_tmp[eg * 64 + a] = part;
            __syncthreads();
#pragma unroll
            for (int j = 0; j < 4; j++) s_Ms[(e0 + j) * 64 + a] += m[j];
            if (tid < 64) {
                float d = 0.f;
#pragma unroll
                for (int g = 0; g < 16; g++) d += s_tmp[g * 64 + tid];
                s_as[tid] += d;
            }
            __syncthreads();
        }
    }
    for (int i = tid; i < 4096; i += 1024) g_Msum[b * 4096 + i] = s_Ms[i];
}

// ---------------- final: att rows, ol = mean(att^2), max (32 rows/block) ------
__global__ void __launch_bounds__(128) k_final(const int* __restrict__ ops,
                                               const float* __restrict__ cIn,
                                               const float* __restrict__ att_init) {
    int b = blockIdx.y;
    int ag = threadIdx.x;           // 0..15 -> a = ag*4..+3
    int ny = threadIdx.y;           // 0..7
    int tid = ny * 16 + ag;
    __shared__ float s_Ms[4096], s_meta[768], s_ai[64];
    __shared__ float s_ti[8][64], s_pr[8][16];
    __shared__ int s_opf[12];
    for (int i = tid; i < 4096; i += 128) s_Ms[i] = g_Msum[b * 4096 + i];
    for (int i = tid; i < 768; i += 128) s_meta[i] = g_meta[b * 768 + i];
    if (tid < 64) s_ai[tid] = att_init[tid];
    if (tid < 12) s_opf[tid] = ops[b * L_ + tid];
    int base = blockIdx.x * 32;
    for (int g4 = 0; g4 < 4; g4++) {
        int n0 = base + g4 * 8;
        __syncthreads();   // staging buffers free (also covers initial staging)
        for (int i = tid; i < 512; i += 128) {
            int r = i >> 6, e = i & 63;
            int n = n0 + r;
            const float* row = (n < C_) ? cIn + (size_t)n * 64
                                        : g_objIn + (size_t)(b * O_ + n - C_) * 64;
            s_ti[r][e] = row[e];
        }
        {
            int r = tid >> 4, c = tid & 15;
            s_pr[r][c] = g_proj[(size_t)(b * N_ + n0 + r) * 16 + c];
        }
        __syncthreads();
        int n = n0 + ny;
        int a0 = ag * 4;
        float v0 = s_ai[a0], v1 = s_ai[a0 + 1], v2 = s_ai[a0 + 2], v3 = s_ai[a0 + 3];
#pragma unroll
        for (int s = 0; s < 12; s++)
            if (s_opf[s] == 1) {
                float pp = s_pr[ny][s];
                v0 += pp * s_meta[s * 64 + a0];
                v1 += pp * s_meta[s * 64 + a0 + 1];
                v2 += pp * s_meta[s * 64 + a0 + 2];
                v3 += pp * s_meta[s * 64 + a0 + 3];
            }
        const float4* Ms4 = (const float4*)s_Ms;
#pragma unroll
        for (int e = 0; e < 64; e++) {
            float ti = s_ti[ny][e];
            float4 m = Ms4[e * 16 + ag];
            v0 += ti * m.x; v1 += ti * m.y; v2 += ti * m.z; v3 += ti * m.w;
        }
        float sq = v0 * v0 + v1 * v1 + v2 * v2 + v3 * v3;
#pragma unroll
        for (int o = 8; o > 0; o >>= 1) sq += __shfl_xor_sync(0xffffffffu, sq, o);
        if (ag == 0) {
            float ol = sq * (1.0f / 64.0f);
            g_ol[b * N_ + n] = ol;
            atomicMax(&g_olmax[b], __float_as_int(ol));  // ol >= 0
        }
    }
}

__global__ void __launch_bounds__(1024) k_soft(float* __restrict__ out) {
    int b = blockIdx.x;
    int tid = threadIdx.x;
    __shared__ float s_red[1024];
    float mx = __int_as_float(g_olmax[b]);
    float lsum = 0.f;
    for (int n = tid; n < N_; n += 1024) lsum += expf(g_ol[b * N_ + n] - mx);
    s_red[tid] = lsum;
    __syncthreads();
    for (int s = 512; s > 0; s >>= 1) {
        if (tid < s) s_red[tid] += s_red[tid + s];
        __syncthreads();
    }
    float lse = logf(s_red[0]) + mx;
    for (int n = tid; n < N_; n += 1024) out[b * N_ + n] = g_ol[b * N_ + n] - lse;
}

// ---------------- launch ------------------------------------------------------
extern "C" void kernel_launch(void* const* d_in, const int* in_sizes, int n_in,
                              void* d_out, int out_size) {
    const float* class_embIn   = (const float*)d_in[0];
    const float* class_embOut  = (const float*)d_in[1];
    const float* attr_embIn    = (const float*)d_in[2];
    const float* attr_embOut   = (const float*)d_in[3];
    const float* concept_embIn = (const float*)d_in[4];
    const float* concept_embOut= (const float*)d_in[5];
    const float* meta_init     = (const float*)d_in[6];
    const float* attention_init= (const float*)d_in[8];
    const float* axon_w1       = (const float*)d_in[9];
    const float* axon_b1       = (const float*)d_in[10];
    const float* axon_w2       = (const float*)d_in[11];
    const float* axon_b2       = (const float*)d_in[12];
    const float* meta_w1       = (const float*)d_in[13];
    const float* meta_b1       = (const float*)d_in[14];
    const float* meta_w2       = (const float*)d_in[15];
    const float* meta_b2       = (const float*)d_in[16];
    const int*   program_ops   = (const int*)d_in[17];
    const int*   program_args  = (const int*)d_in[18];
    const int*   gt_classes    = (const int*)d_in[19];
    const int*   gt_attributes = (const int*)d_in[20];
    float* out = (float*)d_out;

    cudaFuncSetAttribute(k_meta, cudaFuncAttributeMaxDynamicSharedMemorySize,
                         32768 * (int)sizeof(float));

    k_zero<<<(B_ * L_ * H_ * DCOLS / 4 + 255) / 256, 256>>>();
    k_objT1o<<<dim3(O_ / 16, B_), 256>>>(class_embIn, class_embOut, attr_embIn,
                                         attr_embOut, gt_classes, gt_attributes,
                                         axon_w1);
    k_T1c<<<C_ / 16, 256>>>(concept_embOut, axon_w1);
    k_argparg<<<B_ * L_, 256>>>(concept_embOut, program_args, meta_w1, meta_b1);
    k_meta<<<B_, 256, 32768 * sizeof(float)>>>(meta_init, meta_w1, meta_w2,
                                               meta_b2, program_ops);
    k_u<<<B_ * L_, 256>>>(axon_w1, axon_b1);
    k_proj<<<dim3(N_ / 8, B_), 256>>>(concept_embOut);
    k_tinsum<<<dim3(N_ / 64, B_), 64>>>(concept_embIn);
    k_D<<<dim3(N_ / 192, L_, B_), 512>>>(program_ops, concept_embIn);
    k_E<<<dim3(L_, B_), 256>>>(program_ops, axon_w2);
    k_rec<<<B_, 1024>>>(program_ops, axon_b2, attention_init);
    k_final<<<dim3(N_ / 32, B_), dim3(16, 8)>>>(program_ops, concept_embIn,
                                                attention_init);
    k_soft<<<B_, 1024>>>(out);
}

// round 8
// speedup vs baseline: 1.2792x; 1.2792x over previous
#include <cuda_runtime.h>

// Problem constants
constexpr int B_ = 8, L_ = 12, C_ = 4096, O_ = 128, N_ = 4224;
constexpr int E_ = 64, A_ = 64, H_ = 256;
constexpr int DCOLS = 80;  // X cols: 0..63 tIn, 64..75 proj_s, 76 = ones, 77..79 pad

// ---------------- scratch (device globals) ----------------------------------
__device__ __align__(16) float g_objIn[B_ * O_ * E_];
__device__ __align__(16) float g_objOut[B_ * O_ * E_];
__device__ __align__(16) float g_T1c[C_ * H_];
__device__ __align__(16) float g_T1o[B_ * O_ * H_];
__device__ __align__(16) float g_meta[B_ * L_ * A_];
__device__ __align__(16) float g_arg[B_ * L_ * E_];
__device__ __align__(16) float g_proj[B_ * N_ * 16];
__device__ __align__(16) float g_psum[B_ * 16];
__device__ __align__(16) float g_tInsum[B_ * E_];
__device__ __align__(16) float g_D[B_ * L_ * H_ * DCOLS];   // [bt][h][c]
__device__ __align__(16) float g_E[B_ * L_ * DCOLS * 64];   // [bt][c][e'] (transposed)
__device__ __align__(16) float g_Msum[B_ * E_ * A_];
__device__ __align__(16) float g_ol[B_ * N_];
__device__ int g_olmax[B_];

__device__ __forceinline__ unsigned long long pack2(float v) {
    unsigned int b = __float_as_uint(v);
    return ((unsigned long long)b << 32) | b;
}
__device__ __forceinline__ float lo2(unsigned long long v) {
    return __uint_as_float((unsigned)(v & 0xffffffffULL));
}
__device__ __forceinline__ float hi2(unsigned long long v) {
    return __uint_as_float((unsigned)(v >> 32));
}

// ---------------- 1: zero accumulators ---------------------------------------
__global__ void k_zero() {
    int i = blockIdx.x * 256 + threadIdx.x;
    float4 z = make_float4(0.f, 0.f, 0.f, 0.f);
    if (i < B_ * L_ * H_ * DCOLS / 4) ((float4*)g_D)[i] = z;
    if (i < B_ * 16) g_psum[i] = 0.f;
    if (i < B_ * E_) g_tInsum[i] = 0.f;
    if (i < B_) g_olmax[i] = 0;
}

// ---------------- 2: fused obj + T1o (16 objects per block) -------------------
__global__ void __launch_bounds__(256) k_objT1o(
    const float* __restrict__ clsIn, const float* __restrict__ clsOut,
    const float* __restrict__ atIn, const float* __restrict__ atOut,
    const int* __restrict__ gt_cls, const int* __restrict__ gt_attr,
    const float* __restrict__ w1) {
    int tid = threadIdx.x;
    int b = blockIdx.y;
    int o0 = blockIdx.x * 16;
    __shared__ float s_out[1024];   // 16 objOut rows
    __shared__ float s_w[4096];     // 16 e-rows x 256 h
    for (int i = tid; i < 1024; i += 256) {
        int r = i >> 6, e = i & 63;
        int o = o0 + r;
        int cls = gt_cls[b * O_ + o];
        float vi = clsIn[cls * E_ + e];
        float vo = clsOut[cls * E_ + e];
#pragma unroll
        for (int k = 0; k < 8; k++) {
            int at = gt_attr[(b * O_ + o) * 8 + k];
            vi += atIn[at * E_ + e];
            vo += atOut[at * E_ + e];
        }
        g_objIn[(b * O_ + o) * E_ + e] = vi;
        g_objOut[(b * O_ + o) * E_ + e] = vo;
        s_out[i] = vo;
    }
    int h = tid;
    float acc[16];
#pragma unroll
    for (int r = 0; r < 16; r++) acc[r] = 0.f;
    for (int ch = 0; ch < 4; ch++) {
        __syncthreads();
        {
            const float4* src = (const float4*)(w1 + ch * 16 * H_);
            float4* dst = (float4*)s_w;
            for (int i = tid; i < 1024; i += 256) dst[i] = src[i];
        }
        __syncthreads();
#pragma unroll
        for (int e = 0; e < 16; e++) {
            float w = s_w[e * H_ + h];
            int ge = ch * 16 + e;
#pragma unroll
            for (int r = 0; r < 16; r++) acc[r] += s_out[r * 64 + ge] * w;
        }
    }
#pragma unroll
    for (int r = 0; r < 16; r++) g_T1o[(b * O_ + o0 + r) * H_ + h] = acc[r];
}

// ---------------- 3: T1c (16 rows per block) ----------------------------------
__global__ void __launch_bounds__(256) k_T1c(const float* __restrict__ cOut,
                                             const float* __restrict__ w1) {
    int h = threadIdx.x;
    int n0 = blockIdx.x * 16;
    __shared__ float s_emb[1024];
    __shared__ float s_w[4096];
    for (int i = h; i < 1024; i += 256) s_emb[i] = cOut[n0 * E_ + i];
    float acc[16];
#pragma unroll
    for (int r = 0; r < 16; r++) acc[r] = 0.f;
    for (int ch = 0; ch < 4; ch++) {
        __syncthreads();
        {
            const float4* src = (const float4*)(w1 + ch * 16 * H_);
            float4* dst = (float4*)s_w;
            for (int i = h; i < 1024; i += 256) dst[i] = src[i];
        }
        __syncthreads();
#pragma unroll
        for (int e = 0; e < 16; e++) {
            float w = s_w[e * H_ + h];
            int ge = ch * 16 + e;
#pragma unroll
            for (int r = 0; r < 16; r++) acc[r] += s_emb[r * 64 + ge] * w;
        }
    }
#pragma unroll
    for (int r = 0; r < 16; r++) g_T1c[(n0 + r) * H_ + h] = acc[r];
}

// ---------------- 4: meta recurrence (arg gather + parg inlined) --------------
__global__ void __launch_bounds__(256) k_meta(
    const float* __restrict__ meta_init, const float* __restrict__ cOut,
    const int* __restrict__ args,
    const float* __restrict__ mw1, const float* __restrict__ mb1,
    const float* __restrict__ mw2, const float* __restrict__ mb2,
    const int* __restrict__ ops) {
    extern __shared__ float dsm[];
    float* s_w1 = dsm;             // 128*256 floats (128 KB, full meta_w1)
    float* s_w2m = dsm + 32768;    // 256*64 floats (64 KB)
    __shared__ float s_meta[64], s_arg[64], s_h[256], s_part[256];
    int b = blockIdx.x;
    int tid = threadIdx.x;
    {
        const float4* w1_4 = (const float4*)mw1;
        float4* d1 = (float4*)s_w1;
        for (int i = tid; i < 8192; i += 256) d1[i] = w1_4[i];
        const float4* w2_4 = (const float4*)mw2;
        float4* d2 = (float4*)s_w2m;
        for (int i = tid; i < 4096; i += 256) d2[i] = w2_4[i];
    }
    float r_mb1 = mb1[tid];
    float r_mb2 = (tid < 64) ? mb2[tid] : 0.f;
    if (tid < 64) s_meta[tid] = meta_init[tid];
    __syncthreads();
    for (int t = 0; t < L_; t++) {
        if (tid < 64) {
            int ai = args[b * L_ + t];
            float v = cOut[ai * E_ + tid];
            s_arg[tid] = v;
            g_arg[(b * L_ + t) * E_ + tid] = v;
        }
        __syncthreads();
        // pre = mb1 + meta @ w1[0:64] + arg @ w1[64:128]  (4-way ILP)
        float p0 = r_mb1, p1 = 0.f, p2 = 0.f, p3 = 0.f;
#pragma unroll
        for (int a = 0; a < 64; a += 4) {
            p0 += s_meta[a] * s_w1[a * H_ + tid];
            p1 += s_meta[a + 1] * s_w1[(a + 1) * H_ + tid];
            p2 += s_meta[a + 2] * s_w1[(a + 2) * H_ + tid];
            p3 += s_meta[a + 3] * s_w1[(a + 3) * H_ + tid];
        }
#pragma unroll
        for (int e = 0; e < 64; e += 4) {
            p0 += s_arg[e] * s_w1[(64 + e) * H_ + tid];
            p1 += s_arg[e + 1] * s_w1[(65 + e) * H_ + tid];
            p2 += s_arg[e + 2] * s_w1[(66 + e) * H_ + tid];
            p3 += s_arg[e + 3] * s_w1[(67 + e) * H_ + tid];
        }
        s_h[tid] = fmaxf((p0 + p1) + (p2 + p3), 0.f);
        __syncthreads();
        {
            int a = tid & 63;
            int base = (tid >> 6) * 64;
            float q0 = 0.f, q1 = 0.f, q2 = 0.f, q3 = 0.f;
#pragma unroll
            for (int hh = 0; hh < 64; hh += 4) {
                q0 += s_h[base + hh] * s_w2m[(base + hh) * A_ + a];
                q1 += s_h[base + hh + 1] * s_w2m[(base + hh + 1) * A_ + a];
                q2 += s_h[base + hh + 2] * s_w2m[(base + hh + 2) * A_ + a];
                q3 += s_h[base + hh + 3] * s_w2m[(base + hh + 3) * A_ + a];
            }
            s_part[tid] = (q0 + q1) + (q2 + q3);
        }
        __syncthreads();
        if (tid < 64) {
            float nm = r_mb2 + s_part[tid] + s_part[64 + tid] +
                       s_part[128 + tid] + s_part[192 + tid];
            float nv = (ops[b * L_ + t] == 0) ? nm : s_meta[tid];
            s_meta[tid] = nv;
            g_meta[(b * L_ + t) * A_ + tid] = nv;
        }
        __syncthreads();
    }
}

// ---------------- 5: proj (tinsum fused) --------------------------------------
__global__ void __launch_bounds__(256) k_proj(const float* __restrict__ cOut,
                                              const float* __restrict__ cIn) {
    int b = blockIdx.y;
    int tid = threadIdx.x;
    int w = tid >> 5, lane = tid & 31;
    __shared__ float s_arg[768];
    __shared__ float s_p[8][16];
    __shared__ float s_tin[64];
    if (tid < 64) s_tin[tid] = 0.f;
    for (int i = tid; i < 768; i += 256) s_arg[i] = g_arg[b * 768 + i];
    __syncthreads();
    int n = blockIdx.x * 8 + w;
    const float* rowO = (n < C_) ? cOut + (size_t)n * 64
                                 : g_objOut + (size_t)(b * O_ + n - C_) * 64;
    const float* rowI = (n < C_) ? cIn + (size_t)n * 64
                                 : g_objIn + (size_t)(b * O_ + n - C_) * 64;
    float x0 = rowO[lane], x1 = rowO[lane + 32];
    atomicAdd(&s_tin[lane], rowI[lane]);
    atomicAdd(&s_tin[lane + 32], rowI[lane + 32]);
#pragma unroll
    for (int s = 0; s < 12; s++) {
        float p = x0 * s_arg[s * 64 + lane] + x1 * s_arg[s * 64 + 32 + lane];
#pragma unroll
        for (int o = 16; o > 0; o >>= 1) p += __shfl_xor_sync(0xffffffffu, p, o);
        if (lane == 0) s_p[w][s] = p * (1.0f / 64.0f);
    }
    __syncwarp();
    if (lane < 16) {
        float v = (lane < 12) ? s_p[w][lane] : ((lane == 12) ? 1.0f : 0.0f);
        g_proj[(size_t)(b * N_ + n) * 16 + lane] = v;
        if (lane < 12) atomicAdd(&g_psum[b * 16 + lane], v);
    }
    __syncthreads();
    if (tid < 64) atomicAdd(&g_tInsum[b * 64 + tid], s_tin[tid]);
}

// ---------------- 6: big GEMM D_t = Hrel_t^T @ [tIn | proj | 1] ----------------
// u computed in-block: u[h] = ab1[h] + meta @ aw1[64:128,:]
__global__ void __launch_bounds__(256, 2) k_D(const int* __restrict__ ops,
                                              const float* __restrict__ cIn,
                                              const float* __restrict__ aw1,
                                              const float* __restrict__ ab1) {
    int t = blockIdx.y, b = blockIdx.z;
    if (ops[b * L_ + t] != 2) return;
    int h = threadIdx.x;
    __shared__ float s_mt[64];
    __shared__ __align__(16) float s_X[64 * 80];
    if (h < 64) s_mt[h] = g_meta[(b * L_ + t) * A_ + h];
    __syncthreads();
    float u0 = 0.f, u1 = 0.f, u2 = 0.f, u3 = 0.f;
#pragma unroll 4
    for (int a = 0; a < 64; a += 4) {
        u0 += s_mt[a] * __ldg(&aw1[(64 + a) * H_ + h]);
        u1 += s_mt[a + 1] * __ldg(&aw1[(65 + a) * H_ + h]);
        u2 += s_mt[a + 2] * __ldg(&aw1[(66 + a) * H_ + h]);
        u3 += s_mt[a + 3] * __ldg(&aw1[(67 + a) * H_ + h]);
    }
    float uh = ab1[h] + ((u0 + u1) + (u2 + u3));
    unsigned long long acc[40];
#pragma unroll
    for (int j = 0; j < 40; j++) acc[j] = 0ULL;
    int nbase = blockIdx.x * 192;
    for (int tile = 0; tile < 3; tile++) {
        int n0 = nbase + tile * 64;
        {
            float4* dst = (float4*)s_X;
            for (int i = h; i < 1024; i += 256) {
                int r = i >> 4, c = i & 15;
                int n = n0 + r;
                const float4* src = (n < C_)
                    ? (const float4*)cIn + (size_t)n * 16
                    : (const float4*)g_objIn + (size_t)(b * O_ + n - C_) * 16;
                dst[r * 20 + c] = src[c];
            }
            {
                int r = h >> 2, c = h & 3;
                dst[r * 20 + 16 + c] =
                    ((const float4*)g_proj)[(size_t)(b * N_ + n0 + r) * 4 + c];
            }
        }
        __syncthreads();
        float t1a = (n0 < C_) ? g_T1c[n0 * H_ + h]
                              : g_T1o[(b * O_ + n0 - C_) * H_ + h];
        int n1 = n0 + 1;
        float t1b = (n1 < C_) ? g_T1c[n1 * H_ + h]
                              : g_T1o[(b * O_ + n1 - C_) * H_ + h];
        for (int nl = 0; nl < 64; nl++) {
            float hv = fmaxf(t1a + uh, 0.f);
            t1a = t1b;
            if (nl < 62) {
                int n = n0 + nl + 2;
                t1b = (n < C_) ? g_T1c[n * H_ + h]
                               : g_T1o[(b * O_ + n - C_) * H_ + h];
            }
            unsigned long long hv2 = pack2(hv);
            const ulonglong2* xr = (const ulonglong2*)(s_X + nl * 80);
#pragma unroll
            for (int j = 0; j < 20; j++) {
                ulonglong2 p = xr[j];
                asm("fma.rn.f32x2 %0, %1, %2, %0;" : "+l"(acc[2 * j]) : "l"(hv2), "l"(p.x));
                asm("fma.rn.f32x2 %0, %1, %2, %0;" : "+l"(acc[2 * j + 1]) : "l"(hv2), "l"(p.y));
            }
        }
        __syncthreads();
    }
    float* dp = g_D + ((size_t)(b * L_ + t) * H_ + h) * DCOLS;
#pragma unroll
    for (int j = 0; j < 40; j++) {
        asm volatile("red.global.add.v2.f32 [%0], {%1, %2};"
                     :: "l"(dp + 2 * j), "f"(lo2(acc[j])), "f"(hi2(acc[j])) : "memory");
    }
}

// ---------------- 7: k_E: E_t = W2^T @ D_t  (stored transposed [c][e']) --------
__global__ void __launch_bounds__(256) k_E(const int* __restrict__ ops,
                                           const float* __restrict__ w2) {
    int t = blockIdx.x, b = blockIdx.y;
    if (ops[b * L_ + t] != 2) return;
    int tid = threadIdx.x;
    int ep = tid & 63;
    int cq = tid >> 6;
    __shared__ __align__(16) float s_D[64 * 80];
    __shared__ __align__(16) float s_w2[64 * 64];
    unsigned long long acc[10];
#pragma unroll
    for (int j = 0; j < 10; j++) acc[j] = 0ULL;
    size_t dbase = (size_t)(b * L_ + t) * H_ * DCOLS;
    for (int ch = 0; ch < 4; ch++) {
        __syncthreads();
        {
            const float4* src = (const float4*)(g_D + dbase + ch * 64 * DCOLS);
            float4* dst = (float4*)s_D;
            for (int i = tid; i < 1280; i += 256) dst[i] = src[i];
            const float4* wsrc = (const float4*)(w2 + ch * 64 * 64);
            float4* wdst = (float4*)s_w2;
            for (int i = tid; i < 1024; i += 256) wdst[i] = wsrc[i];
        }
        __syncthreads();
        const unsigned long long* D2 = (const unsigned long long*)s_D;
#pragma unroll 8
        for (int hh = 0; hh < 64; hh++) {
            unsigned long long w2v = pack2(s_w2[hh * 64 + ep]);
            const unsigned long long* drow = D2 + hh * 40 + cq * 10;
#pragma unroll
            for (int j = 0; j < 10; j++) {
                asm("fma.rn.f32x2 %0, %1, %2, %0;" : "+l"(acc[j]) : "l"(w2v), "l"(drow[j]));
            }
        }
    }
    float* eb = g_E + (size_t)(b * L_ + t) * DCOLS * 64;
#pragma unroll
    for (int j = 0; j < 10; j++) {
        int c = cq * 20 + 2 * j;
        eb[c * 64 + ep] = lo2(acc[j]);
        eb[(c + 1) * 64 + ep] = hi2(acc[j]);
    }
}

// ---------------- 8: tiny serial recurrence: Msum, attsum ----------------------
__global__ void __launch_bounds__(1024) k_rec(const int* __restrict__ ops,
                                              const float* __restrict__ b2,
                                              const float* __restrict__ att_init) {
    __shared__ __align__(16) float s_Ms[4096];
    __shared__ __align__(16) float s_E[5120];
    __shared__ float s_meta[768], s_tmp[1024];
    __shared__ float s_as[64], s_ai[64], s_tis[64], s_b2[64], s_ps[12];
    __shared__ int s_op[12];
    int b = blockIdx.x, tid = threadIdx.x;
    for (int i = tid; i < 4096; i += 1024) s_Ms[i] = 0.f;
    if (tid < 768) s_meta[tid] = g_meta[b * 768 + tid];
    if (tid < 64) {
        s_ai[tid] = att_init[tid];
        s_as[tid] = (float)N_ * att_init[tid];
        s_tis[tid] = g_tInsum[b * 64 + tid];
        s_b2[tid] = b2[tid];
    }
    if (tid < 12) { s_op[tid] = ops[b * L_ + tid]; s_ps[tid] = g_psum[b * 16 + tid]; }
    __syncthreads();
    const float invN = 1.0f / (float)N_;
    int a = tid & 63, eg = tid >> 6;
    int e0 = eg * 4;
    for (int t = 0; t < L_; t++) {
        int op = s_op[t];
        if (op == 1) {
            if (tid < 64) s_as[tid] += s_ps[t] * s_meta[t * 64 + tid];
            __syncthreads();
        } else if (op == 2) {
            const float* esrc = g_E + (size_t)(b * L_ + t) * 5120;
            for (int i = tid; i < 5120; i += 1024) s_E[i] = esrc[i];
            __syncthreads();
            unsigned long long ai2 = pack2(s_ai[a]);
            unsigned long long acc2[2], bcc2[2];
            {
                ulonglong2 es = *(const ulonglong2*)(s_E + 76 * 64 + e0);
                acc2[0] = 0ULL; acc2[1] = 0ULL; bcc2[0] = 0ULL; bcc2[1] = 0ULL;
                asm("fma.rn.f32x2 %0, %1, %2, %0;" : "+l"(acc2[0]) : "l"(es.x), "l"(ai2));
                asm("fma.rn.f32x2 %0, %1, %2, %0;" : "+l"(acc2[1]) : "l"(es.y), "l"(ai2));
            }
            for (int s = 0; s < t; s++)
                if (s_op[s] == 1) {
                    unsigned long long mv = pack2(s_meta[s * 64 + a]);
                    ulonglong2 er = *(const ulonglong2*)(s_E + (64 + s) * 64 + e0);
                    asm("fma.rn.f32x2 %0, %1, %2, %0;" : "+l"(acc2[0]) : "l"(er.x), "l"(mv));
                    asm("fma.rn.f32x2 %0, %1, %2, %0;" : "+l"(acc2[1]) : "l"(er.y), "l"(mv));
                }
            // E_K @ Msum_pre  (2-way ILP over e)
#pragma unroll 4
            for (int e = 0; e < 64; e += 2) {
                unsigned long long m0 = pack2(s_Ms[e * 64 + a]);
                ulonglong2 k0 = *(const ulonglong2*)(s_E + e * 64 + e0);
                asm("fma.rn.f32x2 %0, %1, %2, %0;" : "+l"(acc2[0]) : "l"(k0.x), "l"(m0));
                asm("fma.rn.f32x2 %0, %1, %2, %0;" : "+l"(acc2[1]) : "l"(k0.y), "l"(m0));
                unsigned long long m1 = pack2(s_Ms[(e + 1) * 64 + a]);
                ulonglong2 k1 = *(const ulonglong2*)(s_E + (e + 1) * 64 + e0);
                asm("fma.rn.f32x2 %0, %1, %2, %0;" : "+l"(bcc2[0]) : "l"(k1.x), "l"(m1));
                asm("fma.rn.f32x2 %0, %1, %2, %0;" : "+l"(bcc2[1]) : "l"(k1.y), "l"(m1));
            }
            float asv = s_as[a];
            float m[4] = {lo2(acc2[0]) + lo2(bcc2[0]), hi2(acc2[0]) + hi2(bcc2[0]),
                          lo2(acc2[1]) + lo2(bcc2[1]), hi2(acc2[1]) + hi2(bcc2[1])};
            float part = 0.f;
#pragma unroll
            for (int j = 0; j < 4; j++) {
                m[j] = (m[j] + s_b2[e0 + j] * asv) * invN;
                part += s_tis[e0 + j] * m[j];
            }
            s_tmp[eg * 64 + a] = part;
            __syncthreads();
#pragma unroll
            for (int j = 0; j < 4; j++) s_Ms[(e0 + j) * 64 + a] += m[j];
            if (tid < 64) {
                float d = 0.f;
#pragma unroll
                for (int g = 0; g < 16; g++) d += s_tmp[g * 64 + tid];
                s_as[tid] += d;
            }
            __syncthreads();
        }
    }
    for (int i = tid; i < 4096; i += 1024) g_Msum[b * 4096 + i] = s_Ms[i];
}

// ---------------- 9: final: att rows, ol, max (32 rows/block) ------------------
__global__ void __launch_bounds__(128) k_final(const int* __restrict__ ops,
                                               const float* __restrict__ cIn,
                                               const float* __restrict__ att_init) {
    int b = blockIdx.y;
    int ag = threadIdx.x;
    int ny = threadIdx.y;
    int tid = ny * 16 + ag;
    __shared__ float s_Ms[4096], s_meta[768], s_ai[64];
    __shared__ float s_ti[8][64], s_pr[8][16];
    __shared__ int s_opf[12];
    for (int i = tid; i < 4096; i += 128) s_Ms[i] = g_Msum[b * 4096 + i];
    for (int i = tid; i < 768; i += 128) s_meta[i] = g_meta[b * 768 + i];
    if (tid < 64) s_ai[tid] = att_init[tid];
    if (tid < 12) s_opf[tid] = ops[b * L_ + tid];
    int base = blockIdx.x * 32;
    for (int g4 = 0; g4 < 4; g4++) {
        int n0 = base + g4 * 8;
        __syncthreads();
        for (int i = tid; i < 512; i += 128) {
            int r = i >> 6, e = i & 63;
            int n = n0 + r;
            const float* row = (n < C_) ? cIn + (size_t)n * 64
                                        : g_objIn + (size_t)(b * O_ + n - C_) * 64;
            s_ti[r][e] = row[e];
        }
        {
            int r = tid >> 4, c = tid & 15;
            s_pr[r][c] = g_proj[(size_t)(b * N_ + n0 + r) * 16 + c];
        }
        __syncthreads();
        int n = n0 + ny;
        int a0 = ag * 4;
        float v0 = s_ai[a0], v1 = s_ai[a0 + 1], v2 = s_ai[a0 + 2], v3 = s_ai[a0 + 3];
#pragma unroll
        for (int s = 0; s < 12; s++)
            if (s_opf[s] == 1) {
                float pp = s_pr[ny][s];
                v0 += pp * s_meta[s * 64 + a0];
                v1 += pp * s_meta[s * 64 + a0 + 1];
                v2 += pp * s_meta[s * 64 + a0 + 2];
                v3 += pp * s_meta[s * 64 + a0 + 3];
            }
        const float4* Ms4 = (const float4*)s_Ms;
#pragma unroll
        for (int e = 0; e < 64; e++) {
            float ti = s_ti[ny][e];
            float4 m = Ms4[e * 16 + ag];
            v0 += ti * m.x; v1 += ti * m.y; v2 += ti * m.z; v3 += ti * m.w;
        }
        float sq = v0 * v0 + v1 * v1 + v2 * v2 + v3 * v3;
#pragma unroll
        for (int o = 8; o > 0; o >>= 1) sq += __shfl_xor_sync(0xffffffffu, sq, o);
        if (ag == 0) {
            float ol = sq * (1.0f / 64.0f);
            g_ol[b * N_ + n] = ol;
            atomicMax(&g_olmax[b], __float_as_int(ol));  // ol >= 0
        }
    }
}

// ---------------- 10: softmax --------------------------------------------------
__global__ void __launch_bounds__(1024) k_soft(float* __restrict__ out) {
    int b = blockIdx.x;
    int tid = threadIdx.x;
    __shared__ float s_red[1024];
    float mx = __int_as_float(g_olmax[b]);
    float lsum = 0.f;
    for (int n = tid; n < N_; n += 1024) lsum += expf(g_ol[b * N_ + n] - mx);
    s_red[tid] = lsum;
    __syncthreads();
    for (int s = 512; s > 0; s >>= 1) {
        if (tid < s) s_red[tid] += s_red[tid + s];
        __syncthreads();
    }
    float lse = logf(s_red[0]) + mx;
    for (int n = tid; n < N_; n += 1024) out[b * N_ + n] = g_ol[b * N_ + n] - lse;
}

// ---------------- launch --------------------------------------------------------
extern "C" void kernel_launch(void* const* d_in, const int* in_sizes, int n_in,
                              void* d_out, int out_size) {
    const float* class_embIn   = (const float*)d_in[0];
    const float* class_embOut  = (const float*)d_in[1];
    const float* attr_embIn    = (const float*)d_in[2];
    const float* attr_embOut   = (const float*)d_in[3];
    const float* concept_embIn = (const float*)d_in[4];
    const float* concept_embOut= (const float*)d_in[5];
    const float* meta_init     = (const float*)d_in[6];
    const float* attention_init= (const float*)d_in[8];
    const float* axon_w1       = (const float*)d_in[9];
    const float* axon_b1       = (const float*)d_in[10];
    const float* axon_w2       = (const float*)d_in[11];
    const float* axon_b2       = (const float*)d_in[12];
    const float* meta_w1       = (const float*)d_in[13];
    const float* meta_b1       = (const float*)d_in[14];
    const float* meta_w2       = (const float*)d_in[15];
    const float* meta_b2       = (const float*)d_in[16];
    const int*   program_ops   = (const int*)d_in[17];
    const int*   program_args  = (const int*)d_in[18];
    const int*   gt_classes    = (const int*)d_in[19];
    const int*   gt_attributes = (const int*)d_in[20];
    float* out = (float*)d_out;

    cudaFuncSetAttribute(k_meta, cudaFuncAttributeMaxDynamicSharedMemorySize,
                         49152 * (int)sizeof(float));  // 192 KB

    k_zero<<<(B_ * L_ * H_ * DCOLS / 4 + 255) / 256, 256>>>();                  // 1
    k_objT1o<<<dim3(O_ / 16, B_), 256>>>(class_embIn, class_embOut, attr_embIn, // 2
                                         attr_embOut, gt_classes, gt_attributes,
                                         axon_w1);
    k_T1c<<<C_ / 16, 256>>>(concept_embOut, axon_w1);                           // 3
    k_meta<<<B_, 256, 49152 * sizeof(float)>>>(meta_init, concept_embOut,       // 4
                                               program_args, meta_w1, meta_b1,
                                               meta_w2, meta_b2, program_ops);
    k_proj<<<dim3(N_ / 8, B_), 256>>>(concept_embOut, concept_embIn);           // 5
    k_D<<<dim3(N_ / 192, L_, B_), 256>>>(program_ops, concept_embIn,            // 6
                                         axon_w1, axon_b1);
    k_E<<<dim3(L_, B_), 256>>>(program_ops, axon_w2);                           // 7
    k_rec<<<B_, 1024>>>(program_ops, axon_b2, attention_init);                  // 8
    k_final<<<dim3(N_ / 32, B_), dim3(16, 8)>>>(program_ops, concept_embIn,     // 9
                                                attention_init);
    k_soft<<<B_, 1024>>>(out);                                                  // 10
}

// round 9
// speedup vs baseline: 1.2920x; 1.0100x over previous
#include <cuda_runtime.h>

// Problem constants
constexpr int B_ = 8, L_ = 12, C_ = 4096, O_ = 128, N_ = 4224;
constexpr int E_ = 64, A_ = 64, H_ = 256;
constexpr int DCOLS = 80;  // X cols: 0..63 tIn, 64..75 proj_s, 76 = ones, 77..79 pad

// ---------------- scratch (device globals) ----------------------------------
__device__ __align__(16) float g_objIn[B_ * O_ * E_];
__device__ __align__(16) float g_objOut[B_ * O_ * E_];
__device__ __align__(16) float g_T1c[C_ * H_];
__device__ __align__(16) float g_T1o[B_ * O_ * H_];
__device__ __align__(16) float g_meta[B_ * L_ * A_];
__device__ __align__(16) float g_arg[B_ * L_ * E_];
__device__ __align__(16) float g_proj[B_ * N_ * 16];
__device__ __align__(16) float g_psum[B_ * 16];
__device__ __align__(16) float g_tInsum[B_ * E_];
__device__ __align__(16) float g_D[B_ * L_ * H_ * DCOLS];   // [bt][h][c]
__device__ __align__(16) float g_E[B_ * L_ * DCOLS * 64];   // [bt][c][e'] (transposed)
__device__ __align__(16) float g_Msum[B_ * E_ * A_];
__device__ __align__(16) float g_ol[B_ * N_];
__device__ int g_olmax[B_];

__device__ __forceinline__ unsigned long long pack2(float v) {
    unsigned int b = __float_as_uint(v);
    return ((unsigned long long)b << 32) | b;
}
__device__ __forceinline__ float lo2(unsigned long long v) {
    return __uint_as_float((unsigned)(v & 0xffffffffULL));
}
__device__ __forceinline__ float hi2(unsigned long long v) {
    return __uint_as_float((unsigned)(v >> 32));
}

// ---------------- 1: fused precompute: T1c | objT1o | zero | arg gather -------
// blocks: [0,256) T1c, [256,320) objT1o, [320,344) zero, [344] arg gather
__global__ void __launch_bounds__(256) k_pre(
    const float* __restrict__ clsIn, const float* __restrict__ clsOut,
    const float* __restrict__ atIn, const float* __restrict__ atOut,
    const int* __restrict__ gt_cls, const int* __restrict__ gt_attr,
    const float* __restrict__ w1, const float* __restrict__ cOut,
    const int* __restrict__ args) {
    int bx = blockIdx.x;
    int tid = threadIdx.x;
    __shared__ float s_emb[1024];
    __shared__ float s_w[4096];

    if (bx < 256) {
        // ---- T1c: 16 concept rows per block ----
        int n0 = bx * 16;
        for (int i = tid; i < 1024; i += 256) s_emb[i] = cOut[n0 * E_ + i];
        float acc[16];
#pragma unroll
        for (int r = 0; r < 16; r++) acc[r] = 0.f;
        for (int ch = 0; ch < 4; ch++) {
            __syncthreads();
            {
                const float4* src = (const float4*)(w1 + ch * 16 * H_);
                float4* dst = (float4*)s_w;
                for (int i = tid; i < 1024; i += 256) dst[i] = src[i];
            }
            __syncthreads();
#pragma unroll
            for (int e = 0; e < 16; e++) {
                float w = s_w[e * H_ + tid];
                int ge = ch * 16 + e;
#pragma unroll
                for (int r = 0; r < 16; r++) acc[r] += s_emb[r * 64 + ge] * w;
            }
        }
#pragma unroll
        for (int r = 0; r < 16; r++) g_T1c[(n0 + r) * H_ + tid] = acc[r];
    } else if (bx < 320) {
        // ---- obj embeddings + T1o: 16 objects per block ----
        int idx = bx - 256;
        int b = idx >> 3;
        int o0 = (idx & 7) * 16;
        for (int i = tid; i < 1024; i += 256) {
            int r = i >> 6, e = i & 63;
            int o = o0 + r;
            int cls = gt_cls[b * O_ + o];
            float vi = clsIn[cls * E_ + e];
            float vo = clsOut[cls * E_ + e];
#pragma unroll
            for (int k = 0; k < 8; k++) {
                int at = gt_attr[(b * O_ + o) * 8 + k];
                vi += atIn[at * E_ + e];
                vo += atOut[at * E_ + e];
            }
            g_objIn[(b * O_ + o) * E_ + e] = vi;
            g_objOut[(b * O_ + o) * E_ + e] = vo;
            s_emb[i] = vo;
        }
        float acc[16];
#pragma unroll
        for (int r = 0; r < 16; r++) acc[r] = 0.f;
        for (int ch = 0; ch < 4; ch++) {
            __syncthreads();
            {
                const float4* src = (const float4*)(w1 + ch * 16 * H_);
                float4* dst = (float4*)s_w;
                for (int i = tid; i < 1024; i += 256) dst[i] = src[i];
            }
            __syncthreads();
#pragma unroll
            for (int e = 0; e < 16; e++) {
                float w = s_w[e * H_ + tid];
                int ge = ch * 16 + e;
#pragma unroll
                for (int r = 0; r < 16; r++) acc[r] += s_emb[r * 64 + ge] * w;
            }
        }
#pragma unroll
        for (int r = 0; r < 16; r++) g_T1o[(b * O_ + o0 + r) * H_ + tid] = acc[r];
    } else if (bx < 344) {
        // ---- zero g_D (+ small accumulators in first block) ----
        int i = (bx - 320) * 256 + tid;   // 0..6143
        float4 z = make_float4(0.f, 0.f, 0.f, 0.f);
        float4* d4 = (float4*)g_D;
#pragma unroll
        for (int j = 0; j < 80; j++) d4[j * 6144 + i] = z;
        if (bx == 320) {
            if (tid < 128) g_psum[tid] = 0.f;
            g_tInsum[tid] = 0.f;
            g_tInsum[256 + tid] = 0.f;
            if (tid < 8) g_olmax[tid] = 0;
        }
    } else {
        // ---- arg gather ----
        for (int i = tid; i < B_ * L_ * E_; i += 256) {
            int bt = i >> 6, e = i & 63;
            g_arg[i] = cOut[args[bt] * E_ + e];
        }
    }
}

// ---------------- 2: meta recurrence (512 threads, split-K) -------------------
__global__ void __launch_bounds__(512) k_meta(
    const float* __restrict__ meta_init,
    const float* __restrict__ mw1, const float* __restrict__ mb1,
    const float* __restrict__ mw2, const float* __restrict__ mb2,
    const int* __restrict__ ops) {
    extern __shared__ float dsm[];
    float* s_w1 = dsm;             // 128*256 (full meta_w1)
    float* s_w2 = dsm + 32768;     // 256*64
    __shared__ float s_in[128];    // [meta(64) | arg(64)]
    __shared__ float s_h[256], s_pre[512], s_part[512];
    int b = blockIdx.x;
    int tid = threadIdx.x;
    {
        const float4* w1_4 = (const float4*)mw1;
        float4* d1 = (float4*)s_w1;
        for (int i = tid; i < 8192; i += 512) d1[i] = w1_4[i];
        const float4* w2_4 = (const float4*)mw2;
        float4* d2 = (float4*)s_w2;
        for (int i = tid; i < 4096; i += 512) d2[i] = w2_4[i];
    }
    float r_mb1 = (tid < 256) ? mb1[tid] : 0.f;
    float r_mb2 = (tid < 64) ? mb2[tid] : 0.f;
    if (tid < 64) s_in[tid] = meta_init[tid];
    __syncthreads();
    int h = tid & 255, half = tid >> 8;          // phase-1 roles
    int a = tid & 63, pq = tid >> 6;             // phase-2 roles
    for (int t = 0; t < L_; t++) {
        if (tid < 64) s_in[64 + tid] = g_arg[(b * L_ + t) * E_ + tid];
        __syncthreads();
        {   // phase 1: split K=128 into two 64-halves
            int base = half * 64;
            float p0 = 0.f, p1 = 0.f, p2 = 0.f, p3 = 0.f;
#pragma unroll
            for (int k = 0; k < 64; k += 4) {
                p0 += s_in[base + k] * s_w1[(base + k) * H_ + h];
                p1 += s_in[base + k + 1] * s_w1[(base + k + 1) * H_ + h];
                p2 += s_in[base + k + 2] * s_w1[(base + k + 2) * H_ + h];
                p3 += s_in[base + k + 3] * s_w1[(base + k + 3) * H_ + h];
            }
            s_pre[tid] = (p0 + p1) + (p2 + p3);
        }
        __syncthreads();
        if (tid < 256) s_h[tid] = fmaxf(r_mb1 + s_pre[tid] + s_pre[256 + tid], 0.f);
        __syncthreads();
        {   // phase 2: split K=256 into eight 32-chunks
            int base = pq * 32;
            float q0 = 0.f, q1 = 0.f;
#pragma unroll
            for (int k = 0; k < 32; k += 2) {
                q0 += s_h[base + k] * s_w2[(base + k) * A_ + a];
                q1 += s_h[base + k + 1] * s_w2[(base + k + 1) * A_ + a];
            }
            s_part[tid] = q0 + q1;
        }
        __syncthreads();
        if (tid < 64) {
            float nm = r_mb2;
#pragma unroll
            for (int g = 0; g < 8; g++) nm += s_part[g * 64 + tid];
            float nv = (ops[b * L_ + t] == 0) ? nm : s_in[tid];
            s_in[tid] = nv;
            g_meta[(b * L_ + t) * A_ + tid] = nv;
        }
        __syncthreads();
    }
}

// ---------------- 3: proj (tinsum fused) --------------------------------------
__global__ void __launch_bounds__(256) k_proj(const float* __restrict__ cOut,
                                              const float* __restrict__ cIn) {
    int b = blockIdx.y;
    int tid = threadIdx.x;
    int w = tid >> 5, lane = tid & 31;
    __shared__ float s_arg[768];
    __shared__ float s_p[8][16];
    __shared__ float s_tin[64];
    if (tid < 64) s_tin[tid] = 0.f;
    for (int i = tid; i < 768; i += 256) s_arg[i] = g_arg[b * 768 + i];
    __syncthreads();
    int n = blockIdx.x * 8 + w;
    const float* rowO = (n < C_) ? cOut + (size_t)n * 64
                                 : g_objOut + (size_t)(b * O_ + n - C_) * 64;
    const float* rowI = (n < C_) ? cIn + (size_t)n * 64
                                 : g_objIn + (size_t)(b * O_ + n - C_) * 64;
    float x0 = rowO[lane], x1 = rowO[lane + 32];
    atomicAdd(&s_tin[lane], rowI[lane]);
    atomicAdd(&s_tin[lane + 32], rowI[lane + 32]);
#pragma unroll
    for (int s = 0; s < 12; s++) {
        float p = x0 * s_arg[s * 64 + lane] + x1 * s_arg[s * 64 + 32 + lane];
#pragma unroll
        for (int o = 16; o > 0; o >>= 1) p += __shfl_xor_sync(0xffffffffu, p, o);
        if (lane == 0) s_p[w][s] = p * (1.0f / 64.0f);
    }
    __syncwarp();
    if (lane < 16) {
        float v = (lane < 12) ? s_p[w][lane] : ((lane == 12) ? 1.0f : 0.0f);
        g_proj[(size_t)(b * N_ + n) * 16 + lane] = v;
        if (lane < 12) atomicAdd(&g_psum[b * 16 + lane], v);
    }
    __syncthreads();
    if (tid < 64) atomicAdd(&g_tInsum[b * 64 + tid], s_tin[tid]);
}

// ---------------- 4: big GEMM D_t = Hrel_t^T @ [tIn | proj | 1] ----------------
__global__ void __launch_bounds__(256, 2) k_D(const int* __restrict__ ops,
                                              const float* __restrict__ cIn,
                                              const float* __restrict__ aw1,
                                              const float* __restrict__ ab1) {
    int t = blockIdx.y, b = blockIdx.z;
    if (ops[b * L_ + t] != 2) return;
    int h = threadIdx.x;
    __shared__ float s_mt[64];
    __shared__ __align__(16) float s_X[64 * 80];
    if (h < 64) s_mt[h] = g_meta[(b * L_ + t) * A_ + h];
    __syncthreads();
    float u0 = 0.f, u1 = 0.f, u2 = 0.f, u3 = 0.f;
#pragma unroll 4
    for (int a = 0; a < 64; a += 4) {
        u0 += s_mt[a] * __ldg(&aw1[(64 + a) * H_ + h]);
        u1 += s_mt[a + 1] * __ldg(&aw1[(65 + a) * H_ + h]);
        u2 += s_mt[a + 2] * __ldg(&aw1[(66 + a) * H_ + h]);
        u3 += s_mt[a + 3] * __ldg(&aw1[(67 + a) * H_ + h]);
    }
    float uh = ab1[h] + ((u0 + u1) + (u2 + u3));
    unsigned long long acc[40];
#pragma unroll
    for (int j = 0; j < 40; j++) acc[j] = 0ULL;
    int nbase = blockIdx.x * 192;
    for (int tile = 0; tile < 3; tile++) {
        int n0 = nbase + tile * 64;
        {
            float4* dst = (float4*)s_X;
            for (int i = h; i < 1024; i += 256) {
                int r = i >> 4, c = i & 15;
                int n = n0 + r;
                const float4* src = (n < C_)
                    ? (const float4*)cIn + (size_t)n * 16
                    : (const float4*)g_objIn + (size_t)(b * O_ + n - C_) * 16;
                dst[r * 20 + c] = src[c];
            }
            {
                int r = h >> 2, c = h & 3;
                dst[r * 20 + 16 + c] =
                    ((const float4*)g_proj)[(size_t)(b * N_ + n0 + r) * 4 + c];
            }
        }
        __syncthreads();
        float t1a = (n0 < C_) ? g_T1c[n0 * H_ + h]
                              : g_T1o[(b * O_ + n0 - C_) * H_ + h];
        int n1 = n0 + 1;
        float t1b = (n1 < C_) ? g_T1c[n1 * H_ + h]
                              : g_T1o[(b * O_ + n1 - C_) * H_ + h];
        for (int nl = 0; nl < 64; nl++) {
            float hv = fmaxf(t1a + uh, 0.f);
            t1a = t1b;
            if (nl < 62) {
                int n = n0 + nl + 2;
                t1b = (n < C_) ? g_T1c[n * H_ + h]
                               : g_T1o[(b * O_ + n - C_) * H_ + h];
            }
            unsigned long long hv2 = pack2(hv);
            const ulonglong2* xr = (const ulonglong2*)(s_X + nl * 80);
#pragma unroll
            for (int j = 0; j < 20; j++) {
                ulonglong2 p = xr[j];
                asm("fma.rn.f32x2 %0, %1, %2, %0;" : "+l"(acc[2 * j]) : "l"(hv2), "l"(p.x));
                asm("fma.rn.f32x2 %0, %1, %2, %0;" : "+l"(acc[2 * j + 1]) : "l"(hv2), "l"(p.y));
            }
        }
        __syncthreads();
    }
    float* dp = g_D + ((size_t)(b * L_ + t) * H_ + h) * DCOLS;
#pragma unroll
    for (int j = 0; j < 40; j++) {
        asm volatile("red.global.add.v2.f32 [%0], {%1, %2};"
                     :: "l"(dp + 2 * j), "f"(lo2(acc[j])), "f"(hi2(acc[j])) : "memory");
    }
}

// ---------------- 5: k_E: E_t = W2^T @ D_t  (stored transposed [c][e']) --------
__global__ void __launch_bounds__(256) k_E(const int* __restrict__ ops,
                                           const float* __restrict__ w2) {
    int t = blockIdx.x, b = blockIdx.y;
    if (ops[b * L_ + t] != 2) return;
    int tid = threadIdx.x;
    int ep = tid & 63;
    int cq = tid >> 6;
    __shared__ __align__(16) float s_D[64 * 80];
    __shared__ __align__(16) float s_w2[64 * 64];
    unsigned long long acc[10];
#pragma unroll
    for (int j = 0; j < 10; j++) acc[j] = 0ULL;
    size_t dbase = (size_t)(b * L_ + t) * H_ * DCOLS;
    for (int ch = 0; ch < 4; ch++) {
        __syncthreads();
        {
            const float4* src = (const float4*)(g_D + dbase + ch * 64 * DCOLS);
            float4* dst = (float4*)s_D;
            for (int i = tid; i < 1280; i += 256) dst[i] = src[i];
            const float4* wsrc = (const float4*)(w2 + ch * 64 * 64);
            float4* wdst = (float4*)s_w2;
            for (int i = tid; i < 1024; i += 256) wdst[i] = wsrc[i];
        }
        __syncthreads();
        const unsigned long long* D2 = (const unsigned long long*)s_D;
#pragma unroll 8
        for (int hh = 0; hh < 64; hh++) {
            unsigned long long w2v = pack2(s_w2[hh * 64 + ep]);
            const unsigned long long* drow = D2 + hh * 40 + cq * 10;
#pragma unroll
            for (int j = 0; j < 10; j++) {
                asm("fma.rn.f32x2 %0, %1, %2, %0;" : "+l"(acc[j]) : "l"(w2v), "l"(drow[j]));
            }
        }
    }
    float* eb = g_E + (size_t)(b * L_ + t) * DCOLS * 64;
#pragma unroll
    for (int j = 0; j < 10; j++) {
        int c = cq * 20 + 2 * j;
        eb[c * 64 + ep] = lo2(acc[j]);
        eb[(c + 1) * 64 + ep] = hi2(acc[j]);
    }
}

// ---------------- 6: tiny serial recurrence: Msum, attsum ----------------------
__global__ void __launch_bounds__(1024) k_rec(const int* __restrict__ ops,
                                              const float* __restrict__ b2,
                                              const float* __restrict__ att_init) {
    __shared__ __align__(16) float s_Ms[4096];
    __shared__ __align__(16) float s_E[5120];
    __shared__ float s_meta[768], s_tmp[1024];
    __shared__ float s_as[64], s_ai[64], s_tis[64], s_b2[64], s_ps[12];
    __shared__ int s_op[12];
    int b = blockIdx.x, tid = threadIdx.x;
    for (int i = tid; i < 4096; i += 1024) s_Ms[i] = 0.f;
    if (tid < 768) s_meta[tid] = g_meta[b * 768 + tid];
    if (tid < 64) {
        s_ai[tid] = att_init[tid];
        s_as[tid] = (float)N_ * att_init[tid];
        s_tis[tid] = g_tInsum[b * 64 + tid];
        s_b2[tid] = b2[tid];
    }
    if (tid < 12) { s_op[tid] = ops[b * L_ + tid]; s_ps[tid] = g_psum[b * 16 + tid]; }
    __syncthreads();
    const float invN = 1.0f / (float)N_;
    int a = tid & 63, eg = tid >> 6;
    int e0 = eg * 4;
    for (int t = 0; t < L_; t++) {
        int op = s_op[t];
        if (op == 1) {
            if (tid < 64) s_as[tid] += s_ps[t] * s_meta[t * 64 + tid];
            __syncthreads();
        } else if (op == 2) {
            const float* esrc = g_E + (size_t)(b * L_ + t) * 5120;
            for (int i = tid; i < 5120; i += 1024) s_E[i] = esrc[i];
            __syncthreads();
            unsigned long long ai2 = pack2(s_ai[a]);
            unsigned long long acc2[2], bcc2[2];
            {
                ulonglong2 es = *(const ulonglong2*)(s_E + 76 * 64 + e0);
                acc2[0] = 0ULL; acc2[1] = 0ULL; bcc2[0] = 0ULL; bcc2[1] = 0ULL;
                asm("fma.rn.f32x2 %0, %1, %2, %0;" : "+l"(acc2[0]) : "l"(es.x), "l"(ai2));
                asm("fma.rn.f32x2 %0, %1, %2, %0;" : "+l"(acc2[1]) : "l"(es.y), "l"(ai2));
            }
            for (int s = 0; s < t; s++)
                if (s_op[s] == 1) {
                    unsigned long long mv = pack2(s_meta[s * 64 + a]);
                    ulonglong2 er = *(const ulonglong2*)(s_E + (64 + s) * 64 + e0);
                    asm("fma.rn.f32x2 %0, %1, %2, %0;" : "+l"(acc2[0]) : "l"(er.x), "l"(mv));
                    asm("fma.rn.f32x2 %0, %1, %2, %0;" : "+l"(acc2[1]) : "l"(er.y), "l"(mv));
                }
#pragma unroll 4
            for (int e = 0; e < 64; e += 2) {
                unsigned long long m0 = pack2(s_Ms[e * 64 + a]);
                ulonglong2 k0 = *(const ulonglong2*)(s_E + e * 64 + e0);
                asm("fma.rn.f32x2 %0, %1, %2, %0;" : "+l"(acc2[0]) : "l"(k0.x), "l"(m0));
                asm("fma.rn.f32x2 %0, %1, %2, %0;" : "+l"(acc2[1]) : "l"(k0.y), "l"(m0));
                unsigned long long m1 = pack2(s_Ms[(e + 1) * 64 + a]);
                ulonglong2 k1 = *(const ulonglong2*)(s_E + (e + 1) * 64 + e0);
                asm("fma.rn.f32x2 %0, %1, %2, %0;" : "+l"(bcc2[0]) : "l"(k1.x), "l"(m1));
                asm("fma.rn.f32x2 %0, %1, %2, %0;" : "+l"(bcc2[1]) : "l"(k1.y), "l"(m1));
            }
            float asv = s_as[a];
            float m[4] = {lo2(acc2[0]) + lo2(bcc2[0]), hi2(acc2[0]) + hi2(bcc2[0]),
                          lo2(acc2[1]) + lo2(bcc2[1]), hi2(acc2[1]) + hi2(bcc2[1])};
            float part = 0.f;
#pragma unroll
            for (int j = 0; j < 4; j++) {
                m[j] = (m[j] + s_b2[e0 + j] * asv) * invN;
                part += s_tis[e0 + j] * m[j];
            }
            s_tmp[eg * 64 + a] = part;
            __syncthreads();
#pragma unroll
            for (int j = 0; j < 4; j++) s_Ms[(e0 + j) * 64 + a] += m[j];
            if (tid < 64) {
                float d = 0.f;
#pragma unroll
                for (int g = 0; g < 16; g++) d += s_tmp[g * 64 + tid];
                s_as[tid] += d;
            }
            __syncthreads();
        }
    }
    for (int i = tid; i < 4096; i += 1024) g_Msum[b * 4096 + i] = s_Ms[i];
}

// ---------------- 7: final: att rows, ol, max (32 rows/block) ------------------
__global__ void __launch_bounds__(128) k_final(const int* __restrict__ ops,
                                               const float* __restrict__ cIn,
                                               const float* __restrict__ att_init) {
    int b = blockIdx.y;
    int ag = threadIdx.x;
    int ny = threadIdx.y;
    int tid = ny * 16 + ag;
    __shared__ float s_Ms[4096], s_meta[768], s_ai[64];
    __shared__ float s_ti[8][64], s_pr[8][16];
    __shared__ int s_opf[12];
    for (int i = tid; i < 4096; i += 128) s_Ms[i] = g_Msum[b * 4096 + i];
    for (int i = tid; i < 768; i += 128) s_meta[i] = g_meta[b * 768 + i];
    if (tid < 64) s_ai[tid] = att_init[tid];
    if (tid < 12) s_opf[tid] = ops[b * L_ + tid];
    int base = blockIdx.x * 32;
    for (int g4 = 0; g4 < 4; g4++) {
        int n0 = base + g4 * 8;
        __syncthreads();
        for (int i = tid; i < 512; i += 128) {
            int r = i >> 6, e = i & 63;
            int n = n0 + r;
            const float* row = (n < C_) ? cIn + (size_t)n * 64
                                        : g_objIn + (size_t)(b * O_ + n - C_) * 64;
            s_ti[r][e] = row[e];
        }
        {
            int r = tid >> 4, c = tid & 15;
            s_pr[r][c] = g_proj[(size_t)(b * N_ + n0 + r) * 16 + c];
        }
        __syncthreads();
        int n = n0 + ny;
        int a0 = ag * 4;
        float v0 = s_ai[a0], v1 = s_ai[a0 + 1], v2 = s_ai[a0 + 2], v3 = s_ai[a0 + 3];
#pragma unroll
        for (int s = 0; s < 12; s++)
            if (s_opf[s] == 1) {
                float pp = s_pr[ny][s];
                v0 += pp * s_meta[s * 64 + a0];
                v1 += pp * s_meta[s * 64 + a0 + 1];
                v2 += pp * s_meta[s * 64 + a0 + 2];
                v3 += pp * s_meta[s * 64 + a0 + 3];
            }
        const float4* Ms4 = (const float4*)s_Ms;
#pragma unroll
        for (int e = 0; e < 64; e++) {
            float ti = s_ti[ny][e];
            float4 m = Ms4[e * 16 + ag];
            v0 += ti * m.x; v1 += ti * m.y; v2 += ti * m.z; v3 += ti * m.w;
        }
        float sq = v0 * v0 + v1 * v1 + v2 * v2 + v3 * v3;
#pragma unroll
        for (int o = 8; o > 0; o >>= 1) sq += __shfl_xor_sync(0xffffffffu, sq, o);
        if (ag == 0) {
            float ol = sq * (1.0f / 64.0f);
            g_ol[b * N_ + n] = ol;
            atomicMax(&g_olmax[b], __float_as_int(ol));  // ol >= 0
        }
    }
}

// ---------------- 8: softmax ----------------------------------------------------
__global__ void __launch_bounds__(1024) k_soft(float* __restrict__ out) {
    int b = blockIdx.x;
    int tid = threadIdx.x;
    __shared__ float s_red[1024];
    float mx = __int_as_float(g_olmax[b]);
    float lsum = 0.f;
    for (int n = tid; n < N_; n += 1024) lsum += expf(g_ol[b * N_ + n] - mx);
    s_red[tid] = lsum;
    __syncthreads();
    for (int s = 512; s > 0; s >>= 1) {
        if (tid < s) s_red[tid] += s_red[tid + s];
        __syncthreads();
    }
    float lse = logf(s_red[0]) + mx;
    for (int n = tid; n < N_; n += 1024) out[b * N_ + n] = g_ol[b * N_ + n] - lse;
}

// ---------------- launch --------------------------------------------------------
extern "C" void kernel_launch(void* const* d_in, const int* in_sizes, int n_in,
                              void* d_out, int out_size) {
    const float* class_embIn   = (const float*)d_in[0];
    const float* class_embOut  = (const float*)d_in[1];
    const float* attr_embIn    = (const float*)d_in[2];
    const float* attr_embOut   = (const float*)d_in[3];
    const float* concept_embIn = (const float*)d_in[4];
    const float* concept_embOut= (const float*)d_in[5];
    const float* meta_init     = (const float*)d_in[6];
    const float* attention_init= (const float*)d_in[8];
    const float* axon_w1       = (const float*)d_in[9];
    const float* axon_b1       = (const float*)d_in[10];
    const float* axon_w2       = (const float*)d_in[11];
    const float* axon_b2       = (const float*)d_in[12];
    const float* meta_w1       = (const float*)d_in[13];
    const float* meta_b1       = (const float*)d_in[14];
    const float* meta_w2       = (const float*)d_in[15];
    const float* meta_b2       = (const float*)d_in[16];
    const int*   program_ops   = (const int*)d_in[17];
    const int*   program_args  = (const int*)d_in[18];
    const int*   gt_classes    = (const int*)d_in[19];
    const int*   gt_attributes = (const int*)d_in[20];
    float* out = (float*)d_out;

    cudaFuncSetAttribute(k_meta, cudaFuncAttributeMaxDynamicSharedMemorySize,
                         49152 * (int)sizeof(float));  // 192 KB

    k_pre<<<345, 256>>>(class_embIn, class_embOut, attr_embIn, attr_embOut,   // 1
                        gt_classes, gt_attributes, axon_w1, concept_embOut,
                        program_args);
    k_meta<<<B_, 512, 49152 * sizeof(float)>>>(meta_init, meta_w1, meta_b1,   // 2
                                               meta_w2, meta_b2, program_ops);
    k_proj<<<dim3(N_ / 8, B_), 256>>>(concept_embOut, concept_embIn);         // 3
    k_D<<<dim3(N_ / 192, L_, B_), 256>>>(program_ops, concept_embIn,          // 4
                                         axon_w1, axon_b1);
    k_E<<<dim3(L_, B_), 256>>>(program_ops, axon_w2);                         // 5
    k_rec<<<B_, 1024>>>(program_ops, axon_b2, attention_init);                // 6
    k_final<<<dim3(N_ / 32, B_), dim3(16, 8)>>>(program_ops, concept_embIn,   // 7
                                                attention_init);
    k_soft<<<B_, 1024>>>(out);                                                // 8
}

// round 10
// speedup vs baseline: 1.3645x; 1.0561x over previous
#include <cuda_runtime.h>

// Problem constants
constexpr int B_ = 8, L_ = 12, C_ = 4096, O_ = 128, N_ = 4224;
constexpr int E_ = 64, A_ = 64, H_ = 256;
constexpr int DCOLS = 80;  // X cols: 0..63 tIn, 64..75 proj_s, 76 = ones, 77..79 pad

// ---------------- scratch (device globals) ----------------------------------
__device__ __align__(16) float g_objIn[B_ * O_ * E_];
__device__ __align__(16) float g_objOut[B_ * O_ * E_];
__device__ __align__(16) float g_T1c[C_ * H_];
__device__ __align__(16) float g_T1o[B_ * O_ * H_];
__device__ __align__(16) float g_meta[B_ * L_ * A_];
__device__ __align__(16) float g_arg[B_ * L_ * E_];
__device__ __align__(16) float g_proj[B_ * N_ * 16];
__device__ __align__(16) float g_psum[B_ * 16];
__device__ __align__(16) float g_tInsum[B_ * E_];
__device__ __align__(16) float g_D[B_ * L_ * H_ * DCOLS];   // [bt][h][c]
__device__ __align__(16) float g_E[B_ * L_ * DCOLS * 64];   // [bt][c][e'] (transposed)
__device__ __align__(16) float g_Msum[B_ * E_ * A_];
__device__ __align__(16) float g_ol[B_ * N_];
__device__ int g_olmax[B_];

__device__ __forceinline__ unsigned long long pack2(float v) {
    unsigned int b = __float_as_uint(v);
    return ((unsigned long long)b << 32) | b;
}
__device__ __forceinline__ float lo2(unsigned long long v) {
    return __uint_as_float((unsigned)(v & 0xffffffffULL));
}
__device__ __forceinline__ float hi2(unsigned long long v) {
    return __uint_as_float((unsigned)(v >> 32));
}

// ---------------- 1: fused precompute: T1c | objT1o | zero | arg gather -------
// blocks: [0,256) T1c, [256,320) objT1o, [320,344) zero, [344] arg gather
__global__ void __launch_bounds__(256) k_pre(
    const float* __restrict__ clsIn, const float* __restrict__ clsOut,
    const float* __restrict__ atIn, const float* __restrict__ atOut,
    const int* __restrict__ gt_cls, const int* __restrict__ gt_attr,
    const float* __restrict__ w1, const float* __restrict__ cOut,
    const int* __restrict__ args) {
    int bx = blockIdx.x;
    int tid = threadIdx.x;
    __shared__ float s_emb[1024];
    __shared__ float s_w[4096];

    if (bx < 256) {
        int n0 = bx * 16;
        for (int i = tid; i < 1024; i += 256) s_emb[i] = cOut[n0 * E_ + i];
        float acc[16];
#pragma unroll
        for (int r = 0; r < 16; r++) acc[r] = 0.f;
        for (int ch = 0; ch < 4; ch++) {
            __syncthreads();
            {
                const float4* src = (const float4*)(w1 + ch * 16 * H_);
                float4* dst = (float4*)s_w;
                for (int i = tid; i < 1024; i += 256) dst[i] = src[i];
            }
            __syncthreads();
#pragma unroll
            for (int e = 0; e < 16; e++) {
                float w = s_w[e * H_ + tid];
                int ge = ch * 16 + e;
#pragma unroll
                for (int r = 0; r < 16; r++) acc[r] += s_emb[r * 64 + ge] * w;
            }
        }
#pragma unroll
        for (int r = 0; r < 16; r++) g_T1c[(n0 + r) * H_ + tid] = acc[r];
    } else if (bx < 320) {
        int idx = bx - 256;
        int b = idx >> 3;
        int o0 = (idx & 7) * 16;
        for (int i = tid; i < 1024; i += 256) {
            int r = i >> 6, e = i & 63;
            int o = o0 + r;
            int cls = gt_cls[b * O_ + o];
            float vi = clsIn[cls * E_ + e];
            float vo = clsOut[cls * E_ + e];
#pragma unroll
            for (int k = 0; k < 8; k++) {
                int at = gt_attr[(b * O_ + o) * 8 + k];
                vi += atIn[at * E_ + e];
                vo += atOut[at * E_ + e];
            }
            g_objIn[(b * O_ + o) * E_ + e] = vi;
            g_objOut[(b * O_ + o) * E_ + e] = vo;
            s_emb[i] = vo;
        }
        float acc[16];
#pragma unroll
        for (int r = 0; r < 16; r++) acc[r] = 0.f;
        for (int ch = 0; ch < 4; ch++) {
            __syncthreads();
            {
                const float4* src = (const float4*)(w1 + ch * 16 * H_);
                float4* dst = (float4*)s_w;
                for (int i = tid; i < 1024; i += 256) dst[i] = src[i];
            }
            __syncthreads();
#pragma unroll
            for (int e = 0; e < 16; e++) {
                float w = s_w[e * H_ + tid];
                int ge = ch * 16 + e;
#pragma unroll
                for (int r = 0; r < 16; r++) acc[r] += s_emb[r * 64 + ge] * w;
            }
        }
#pragma unroll
        for (int r = 0; r < 16; r++) g_T1o[(b * O_ + o0 + r) * H_ + tid] = acc[r];
    } else if (bx < 344) {
        int i = (bx - 320) * 256 + tid;   // 0..6143
        float4 z = make_float4(0.f, 0.f, 0.f, 0.f);
        float4* d4 = (float4*)g_D;
#pragma unroll
        for (int j = 0; j < 80; j++) d4[j * 6144 + i] = z;
        if (bx == 320) {
            if (tid < 128) g_psum[tid] = 0.f;
            g_tInsum[tid] = 0.f;
            g_tInsum[256 + tid] = 0.f;
            if (tid < 8) g_olmax[tid] = 0;
        }
    } else {
        for (int i = tid; i < B_ * L_ * E_; i += 256) {
            int bt = i >> 6, e = i & 63;
            g_arg[i] = cOut[args[bt] * E_ + e];
        }
    }
}

// ---------------- 2: meta recurrence (512 threads, split-K) -------------------
__global__ void __launch_bounds__(512) k_meta(
    const float* __restrict__ meta_init,
    const float* __restrict__ mw1, const float* __restrict__ mb1,
    const float* __restrict__ mw2, const float* __restrict__ mb2,
    const int* __restrict__ ops) {
    extern __shared__ float dsm[];
    float* s_w1 = dsm;             // 128*256 (full meta_w1)
    float* s_w2 = dsm + 32768;     // 256*64
    __shared__ float s_in[128];    // [meta(64) | arg(64)]
    __shared__ float s_h[256], s_pre[512], s_part[512];
    int b = blockIdx.x;
    int tid = threadIdx.x;
    {
        const float4* w1_4 = (const float4*)mw1;
        float4* d1 = (float4*)s_w1;
        for (int i = tid; i < 8192; i += 512) d1[i] = w1_4[i];
        const float4* w2_4 = (const float4*)mw2;
        float4* d2 = (float4*)s_w2;
        for (int i = tid; i < 4096; i += 512) d2[i] = w2_4[i];
    }
    float r_mb1 = (tid < 256) ? mb1[tid] : 0.f;
    float r_mb2 = (tid < 64) ? mb2[tid] : 0.f;
    if (tid < 64) s_in[tid] = meta_init[tid];
    __syncthreads();
    int h = tid & 255, half = tid >> 8;
    int a = tid & 63, pq = tid >> 6;
    for (int t = 0; t < L_; t++) {
        if (tid < 64) s_in[64 + tid] = g_arg[(b * L_ + t) * E_ + tid];
        __syncthreads();
        {
            int base = half * 64;
            float p0 = 0.f, p1 = 0.f, p2 = 0.f, p3 = 0.f;
#pragma unroll
            for (int k = 0; k < 64; k += 4) {
                p0 += s_in[base + k] * s_w1[(base + k) * H_ + h];
                p1 += s_in[base + k + 1] * s_w1[(base + k + 1) * H_ + h];
                p2 += s_in[base + k + 2] * s_w1[(base + k + 2) * H_ + h];
                p3 += s_in[base + k + 3] * s_w1[(base + k + 3) * H_ + h];
            }
            s_pre[tid] = (p0 + p1) + (p2 + p3);
        }
        __syncthreads();
        if (tid < 256) s_h[tid] = fmaxf(r_mb1 + s_pre[tid] + s_pre[256 + tid], 0.f);
        __syncthreads();
        {
            int base = pq * 32;
            float q0 = 0.f, q1 = 0.f;
#pragma unroll
            for (int k = 0; k < 32; k += 2) {
                q0 += s_h[base + k] * s_w2[(base + k) * A_ + a];
                q1 += s_h[base + k + 1] * s_w2[(base + k + 1) * A_ + a];
            }
            s_part[tid] = q0 + q1;
        }
        __syncthreads();
        if (tid < 64) {
            float nm = r_mb2;
#pragma unroll
            for (int g = 0; g < 8; g++) nm += s_part[g * 64 + tid];
            float nv = (ops[b * L_ + t] == 0) ? nm : s_in[tid];
            s_in[tid] = nv;
            g_meta[(b * L_ + t) * A_ + tid] = nv;
        }
        __syncthreads();
    }
}

// ---------------- 3: proj (tinsum fused) --------------------------------------
__global__ void __launch_bounds__(256) k_proj(const float* __restrict__ cOut,
                                              const float* __restrict__ cIn) {
    int b = blockIdx.y;
    int tid = threadIdx.x;
    int w = tid >> 5, lane = tid & 31;
    __shared__ float s_arg[768];
    __shared__ float s_p[8][16];
    __shared__ float s_tin[64];
    if (tid < 64) s_tin[tid] = 0.f;
    for (int i = tid; i < 768; i += 256) s_arg[i] = g_arg[b * 768 + i];
    __syncthreads();
    int n = blockIdx.x * 8 + w;
    const float* rowO = (n < C_) ? cOut + (size_t)n * 64
                                 : g_objOut + (size_t)(b * O_ + n - C_) * 64;
    const float* rowI = (n < C_) ? cIn + (size_t)n * 64
                                 : g_objIn + (size_t)(b * O_ + n - C_) * 64;
    float x0 = rowO[lane], x1 = rowO[lane + 32];
    atomicAdd(&s_tin[lane], rowI[lane]);
    atomicAdd(&s_tin[lane + 32], rowI[lane + 32]);
#pragma unroll
    for (int s = 0; s < 12; s++) {
        float p = x0 * s_arg[s * 64 + lane] + x1 * s_arg[s * 64 + 32 + lane];
#pragma unroll
        for (int o = 16; o > 0; o >>= 1) p += __shfl_xor_sync(0xffffffffu, p, o);
        if (lane == 0) s_p[w][s] = p * (1.0f / 64.0f);
    }
    __syncwarp();
    if (lane < 16) {
        float v = (lane < 12) ? s_p[w][lane] : ((lane == 12) ? 1.0f : 0.0f);
        g_proj[(size_t)(b * N_ + n) * 16 + lane] = v;
        if (lane < 12) atomicAdd(&g_psum[b * 16 + lane], v);
    }
    __syncthreads();
    if (tid < 64) atomicAdd(&g_tInsum[b * 64 + tid], s_tin[tid]);
}

// ---------------- 4: big GEMM D_t = Hrel_t^T @ [tIn | proj | 1] ----------------
// Register-tiled 4h x 20c per thread: cg = tid>>6 (c-quarter), hg = tid&63.
__global__ void __launch_bounds__(256, 2) k_D(const int* __restrict__ ops,
                                              const float* __restrict__ cIn,
                                              const float* __restrict__ aw1,
                                              const float* __restrict__ ab1) {
    int t = blockIdx.y, b = blockIdx.z;
    if (ops[b * L_ + t] != 2) return;
    int tid = threadIdx.x;
    int cg = tid >> 6;        // c base = cg*20
    int hg = tid & 63;        // h base = hg*4
    __shared__ float s_mt[64];
    __shared__ __align__(16) float s_u[256];
    __shared__ __align__(16) float s_X[64 * 80];
    if (tid < 64) s_mt[tid] = g_meta[(b * L_ + t) * A_ + tid];
    __syncthreads();
    {   // u[h] cooperative: thread tid computes h = tid
        float u0 = 0.f, u1 = 0.f, u2 = 0.f, u3 = 0.f;
#pragma unroll 4
        for (int a = 0; a < 64; a += 4) {
            u0 += s_mt[a] * __ldg(&aw1[(64 + a) * H_ + tid]);
            u1 += s_mt[a + 1] * __ldg(&aw1[(65 + a) * H_ + tid]);
            u2 += s_mt[a + 2] * __ldg(&aw1[(66 + a) * H_ + tid]);
            u3 += s_mt[a + 3] * __ldg(&aw1[(67 + a) * H_ + tid]);
        }
        s_u[tid] = ab1[tid] + ((u0 + u1) + (u2 + u3));
    }
    __syncthreads();
    float4 uv = *(const float4*)(s_u + hg * 4);

    unsigned long long acc[40];   // [i=h-sub][j=0..9] -> acc[i*10+j]
#pragma unroll
    for (int j = 0; j < 40; j++) acc[j] = 0ULL;

    const float4* T1c4 = (const float4*)g_T1c;
    const float4* T1o4 = (const float4*)g_T1o;
    int nbase = blockIdx.x * 192;
    for (int tile = 0; tile < 3; tile++) {
        int n0 = nbase + tile * 64;
        if (tile) __syncthreads();   // previous X reads done
        {
            float4* dst = (float4*)s_X;
            for (int i = tid; i < 1024; i += 256) {
                int r = i >> 4, c = i & 15;
                int n = n0 + r;
                const float4* src = (n < C_)
                    ? (const float4*)cIn + (size_t)n * 16
                    : (const float4*)g_objIn + (size_t)(b * O_ + n - C_) * 16;
                dst[r * 20 + c] = src[c];
            }
            {
                int r = tid >> 2, c = tid & 3;
                dst[r * 20 + 16 + c] =
                    ((const float4*)g_proj)[(size_t)(b * N_ + n0 + r) * 4 + c];
            }
        }
        __syncthreads();
        // depth-2 prefetch of T1 float4 rows
        float4 t1a = (n0 < C_) ? T1c4[(size_t)n0 * 64 + hg]
                               : T1o4[((size_t)(b * O_ + n0 - C_)) * 64 + hg];
        int n1 = n0 + 1;
        float4 t1b = (n1 < C_) ? T1c4[(size_t)n1 * 64 + hg]
                               : T1o4[((size_t)(b * O_ + n1 - C_)) * 64 + hg];
        for (int nl = 0; nl < 64; nl++) {
            float4 cur = t1a;
            t1a = t1b;
            if (nl < 62) {
                int n = n0 + nl + 2;
                t1b = (n < C_) ? T1c4[(size_t)n * 64 + hg]
                               : T1o4[((size_t)(b * O_ + n - C_)) * 64 + hg];
            }
            unsigned long long hv2_0 = pack2(fmaxf(cur.x + uv.x, 0.f));
            unsigned long long hv2_1 = pack2(fmaxf(cur.y + uv.y, 0.f));
            unsigned long long hv2_2 = pack2(fmaxf(cur.z + uv.z, 0.f));
            unsigned long long hv2_3 = pack2(fmaxf(cur.w + uv.w, 0.f));
            const ulonglong2* xr = (const ulonglong2*)(s_X + nl * 80 + cg * 20);
#pragma unroll
            for (int j = 0; j < 5; j++) {
                ulonglong2 p = xr[j];
                asm("fma.rn.f32x2 %0, %1, %2, %0;" : "+l"(acc[0 * 10 + 2 * j]) : "l"(hv2_0), "l"(p.x));
                asm("fma.rn.f32x2 %0, %1, %2, %0;" : "+l"(acc[0 * 10 + 2 * j + 1]) : "l"(hv2_0), "l"(p.y));
                asm("fma.rn.f32x2 %0, %1, %2, %0;" : "+l"(acc[1 * 10 + 2 * j]) : "l"(hv2_1), "l"(p.x));
                asm("fma.rn.f32x2 %0, %1, %2, %0;" : "+l"(acc[1 * 10 + 2 * j + 1]) : "l"(hv2_1), "l"(p.y));
                asm("fma.rn.f32x2 %0, %1, %2, %0;" : "+l"(acc[2 * 10 + 2 * j]) : "l"(hv2_2), "l"(p.x));
                asm("fma.rn.f32x2 %0, %1, %2, %0;" : "+l"(acc[2 * 10 + 2 * j + 1]) : "l"(hv2_2), "l"(p.y));
                asm("fma.rn.f32x2 %0, %1, %2, %0;" : "+l"(acc[3 * 10 + 2 * j]) : "l"(hv2_3), "l"(p.x));
                asm("fma.rn.f32x2 %0, %1, %2, %0;" : "+l"(acc[3 * 10 + 2 * j + 1]) : "l"(hv2_3), "l"(p.y));
            }
        }
    }
#pragma unroll
    for (int i = 0; i < 4; i++) {
        float* dp = g_D + ((size_t)(b * L_ + t) * H_ + hg * 4 + i) * DCOLS + cg * 20;
#pragma unroll
        for (int j = 0; j < 10; j++) {
            asm volatile("red.global.add.v2.f32 [%0], {%1, %2};"
                         :: "l"(dp + 2 * j), "f"(lo2(acc[i * 10 + j])),
                            "f"(hi2(acc[i * 10 + j])) : "memory");
        }
    }
}

// ---------------- 5: k_E: E_t = W2^T @ D_t  (stored transposed [c][e']) --------
__global__ void __launch_bounds__(256) k_E(const int* __restrict__ ops,
                                           const float* __restrict__ w2) {
    int t = blockIdx.x, b = blockIdx.y;
    if (ops[b * L_ + t] != 2) return;
    int tid = threadIdx.x;
    int ep = tid & 63;
    int cq = tid >> 6;
    __shared__ __align__(16) float s_D[64 * 80];
    __shared__ __align__(16) float s_w2[64 * 64];
    unsigned long long acc[10];
#pragma unroll
    for (int j = 0; j < 10; j++) acc[j] = 0ULL;
    size_t dbase = (size_t)(b * L_ + t) * H_ * DCOLS;
    for (int ch = 0; ch < 4; ch++) {
        __syncthreads();
        {
            const float4* src = (const float4*)(g_D + dbase + ch * 64 * DCOLS);
            float4* dst = (float4*)s_D;
            for (int i = tid; i < 1280; i += 256) dst[i] = src[i];
            const float4* wsrc = (const float4*)(w2 + ch * 64 * 64);
            float4* wdst = (float4*)s_w2;
            for (int i = tid; i < 1024; i += 256) wdst[i] = wsrc[i];
        }
        __syncthreads();
        const unsigned long long* D2 = (const unsigned long long*)s_D;
#pragma unroll 8
        for (int hh = 0; hh < 64; hh++) {
            unsigned long long w2v = pack2(s_w2[hh * 64 + ep]);
            const unsigned long long* drow = D2 + hh * 40 + cq * 10;
#pragma unroll
            for (int j = 0; j < 10; j++) {
                asm("fma.rn.f32x2 %0, %1, %2, %0;" : "+l"(acc[j]) : "l"(w2v), "l"(drow[j]));
            }
        }
    }
    float* eb = g_E + (size_t)(b * L_ + t) * DCOLS * 64;
#pragma unroll
    for (int j = 0; j < 10; j++) {
        int c = cq * 20 + 2 * j;
        eb[c * 64 + ep] = lo2(acc[j]);
        eb[(c + 1) * 64 + ep] = hi2(acc[j]);
    }
}

// ---------------- 6: tiny serial recurrence: Msum, attsum ----------------------
__global__ void __launch_bounds__(1024) k_rec(const int* __restrict__ ops,
                                              const float* __restrict__ b2,
                                              const float* __restrict__ att_init) {
    __shared__ __align__(16) float s_Ms[4096];
    __shared__ __align__(16) float s_E[5120];
    __shared__ float s_meta[768], s_tmp[1024];
    __shared__ float s_as[64], s_ai[64], s_tis[64], s_b2[64], s_ps[12];
    __shared__ int s_op[12];
    int b = blockIdx.x, tid = threadIdx.x;
    for (int i = tid; i < 4096; i += 1024) s_Ms[i] = 0.f;
    if (tid < 768) s_meta[tid] = g_meta[b * 768 + tid];
    if (tid < 64) {
        s_ai[tid] = att_init[tid];
        s_as[tid] = (float)N_ * att_init[tid];
        s_tis[tid] = g_tInsum[b * 64 + tid];
        s_b2[tid] = b2[tid];
    }
    if (tid < 12) { s_op[tid] = ops[b * L_ + tid]; s_ps[tid] = g_psum[b * 16 + tid]; }
    __syncthreads();
    const float invN = 1.0f / (float)N_;
    int a = tid & 63, eg = tid >> 6;
    int e0 = eg * 4;
    for (int t = 0; t < L_; t++) {
        int op = s_op[t];
        if (op == 1) {
            if (tid < 64) s_as[tid] += s_ps[t] * s_meta[t * 64 + tid];
            __syncthreads();
        } else if (op == 2) {
            const float* esrc = g_E + (size_t)(b * L_ + t) * 5120;
            for (int i = tid; i < 5120; i += 1024) s_E[i] = esrc[i];
            __syncthreads();
            unsigned long long ai2 = pack2(s_ai[a]);
            unsigned long long acc2[2], bcc2[2];
            {
                ulonglong2 es = *(const ulonglong2*)(s_E + 76 * 64 + e0);
                acc2[0] = 0ULL; acc2[1] = 0ULL; bcc2[0] = 0ULL; bcc2[1] = 0ULL;
                asm("fma.rn.f32x2 %0, %1, %2, %0;" : "+l"(acc2[0]) : "l"(es.x), "l"(ai2));
                asm("fma.rn.f32x2 %0, %1, %2, %0;" : "+l"(acc2[1]) : "l"(es.y), "l"(ai2));
            }
            for (int s = 0; s < t; s++)
                if (s_op[s] == 1) {
                    unsigned long long mv = pack2(s_meta[s * 64 + a]);
                    ulonglong2 er = *(const ulonglong2*)(s_E + (64 + s) * 64 + e0);
                    asm("fma.rn.f32x2 %0, %1, %2, %0;" : "+l"(acc2[0]) : "l"(er.x), "l"(mv));
                    asm("fma.rn.f32x2 %0, %1, %2, %0;" : "+l"(acc2[1]) : "l"(er.y), "l"(mv));
                }
#pragma unroll 4
            for (int e = 0; e < 64; e += 2) {
                unsigned long long m0 = pack2(s_Ms[e * 64 + a]);
                ulonglong2 k0 = *(const ulonglong2*)(s_E + e * 64 + e0);
                asm("fma.rn.f32x2 %0, %1, %2, %0;" : "+l"(acc2[0]) : "l"(k0.x), "l"(m0));
                asm("fma.rn.f32x2 %0, %1, %2, %0;" : "+l"(acc2[1]) : "l"(k0.y), "l"(m0));
                unsigned long long m1 = pack2(s_Ms[(e + 1) * 64 + a]);
                ulonglong2 k1 = *(const ulonglong2*)(s_E + (e + 1) * 64 + e0);
                asm("fma.rn.f32x2 %0, %1, %2, %0;" : "+l"(bcc2[0]) : "l"(k1.x), "l"(m1));
                asm("fma.rn.f32x2 %0, %1, %2, %0;" : "+l"(bcc2[1]) : "l"(k1.y), "l"(m1));
            }
            float asv = s_as[a];
            float m[4] = {lo2(acc2[0]) + lo2(bcc2[0]), hi2(acc2[0]) + hi2(bcc2[0]),
                          lo2(acc2[1]) + lo2(bcc2[1]), hi2(acc2[1]) + hi2(bcc2[1])};
            float part = 0.f;
#pragma unroll
            for (int j = 0; j < 4; j++) {
                m[j] = (m[j] + s_b2[e0 + j] * asv) * invN;
                part += s_tis[e0 + j] * m[j];
            }
            s_tmp[eg * 64 + a] = part;
            __syncthreads();
#pragma unroll
            for (int j = 0; j < 4; j++) s_Ms[(e0 + j) * 64 + a] += m[j];
            if (tid < 64) {
                float d = 0.f;
#pragma unroll
                for (int g = 0; g < 16; g++) d += s_tmp[g * 64 + tid];
                s_as[tid] += d;
            }
            __syncthreads();
        }
    }
    for (int i = tid; i < 4096; i += 1024) g_Msum[b * 4096 + i] = s_Ms[i];
}

// ---------------- 7: final: att rows, ol, max (32 rows/block) ------------------
__global__ void __launch_bounds__(128) k_final(const int* __restrict__ ops,
                                               const float* __restrict__ cIn,
                                               const float* __restrict__ att_init) {
    int b = blockIdx.y;
    int ag = threadIdx.x;
    int ny = threadIdx.y;
    int tid = ny * 16 + ag;
    __shared__ float s_Ms[4096], s_meta[768], s_ai[64];
    __shared__ float s_ti[8][64], s_pr[8][16];
    __shared__ int s_opf[12];
    for (int i = tid; i < 4096; i += 128) s_Ms[i] = g_Msum[b * 4096 + i];
    for (int i = tid; i < 768; i += 128) s_meta[i] = g_meta[b * 768 + i];
    if (tid < 64) s_ai[tid] = att_init[tid];
    if (tid < 12) s_opf[tid] = ops[b * L_ + tid];
    int base = blockIdx.x * 32;
    for (int g4 = 0; g4 < 4; g4++) {
        int n0 = base + g4 * 8;
        __syncthreads();
        for (int i = tid; i < 512; i += 128) {
            int r = i >> 6, e = i & 63;
            int n = n0 + r;
            const float* row = (n < C_) ? cIn + (size_t)n * 64
                                        : g_objIn + (size_t)(b * O_ + n - C_) * 64;
            s_ti[r][e] = row[e];
        }
        {
            int r = tid >> 4, c = tid & 15;
            s_pr[r][c] = g_proj[(size_t)(b * N_ + n0 + r) * 16 + c];
        }
        __syncthreads();
        int n = n0 + ny;
        int a0 = ag * 4;
        float v0 = s_ai[a0], v1 = s_ai[a0 + 1], v2 = s_ai[a0 + 2], v3 = s_ai[a0 + 3];
#pragma unroll
        for (int s = 0; s < 12; s++)
            if (s_opf[s] == 1) {
                float pp = s_pr[ny][s];
                v0 += pp * s_meta[s * 64 + a0];
                v1 += pp * s_meta[s * 64 + a0 + 1];
                v2 += pp * s_meta[s * 64 + a0 + 2];
                v3 += pp * s_meta[s * 64 + a0 + 3];
            }
        const float4* Ms4 = (const float4*)s_Ms;
#pragma unroll
        for (int e = 0; e < 64; e++) {
            float ti = s_ti[ny][e];
            float4 m = Ms4[e * 16 + ag];
            v0 += ti * m.x; v1 += ti * m.y; v2 += ti * m.z; v3 += ti * m.w;
        }
        float sq = v0 * v0 + v1 * v1 + v2 * v2 + v3 * v3;
#pragma unroll
        for (int o = 8; o > 0; o >>= 1) sq += __shfl_xor_sync(0xffffffffu, sq, o);
        if (ag == 0) {
            float ol = sq * (1.0f / 64.0f);
            g_ol[b * N_ + n] = ol;
            atomicMax(&g_olmax[b], __float_as_int(ol));  // ol >= 0
        }
    }
}

// ---------------- 8: softmax ----------------------------------------------------
__global__ void __launch_bounds__(1024) k_soft(float* __restrict__ out) {
    int b = blockIdx.x;
    int tid = threadIdx.x;
    __shared__ float s_red[1024];
    float mx = __int_as_float(g_olmax[b]);
    float lsum = 0.f;
    for (int n = tid; n < N_; n += 1024) lsum += expf(g_ol[b * N_ + n] - mx);
    s_red[tid] = lsum;
    __syncthreads();
    for (int s = 512; s > 0; s >>= 1) {
        if (tid < s) s_red[tid] += s_red[tid + s];
        __syncthreads();
    }
    float lse = logf(s_red[0]) + mx;
    for (int n = tid; n < N_; n += 1024) out[b * N_ + n] = g_ol[b * N_ + n] - lse;
}

// ---------------- launch --------------------------------------------------------
extern "C" void kernel_launch(void* const* d_in, const int* in_sizes, int n_in,
                              void* d_out, int out_size) {
    const float* class_embIn   = (const float*)d_in[0];
    const float* class_embOut  = (const float*)d_in[1];
    const float* attr_embIn    = (const float*)d_in[2];
    const float* attr_embOut   = (const float*)d_in[3];
    const float* concept_embIn = (const float*)d_in[4];
    const float* concept_embOut= (const float*)d_in[5];
    const float* meta_init     = (const float*)d_in[6];
    const float* attention_init= (const float*)d_in[8];
    const float* axon_w1       = (const float*)d_in[9];
    const float* axon_b1       = (const float*)d_in[10];
    const float* axon_w2       = (const float*)d_in[11];
    const float* axon_b2       = (const float*)d_in[12];
    const float* meta_w1       = (const float*)d_in[13];
    const float* meta_b1       = (const float*)d_in[14];
    const float* meta_w2       = (const float*)d_in[15];
    const float* meta_b2       = (const float*)d_in[16];
    const int*   program_ops   = (const int*)d_in[17];
    const int*   program_args  = (const int*)d_in[18];
    const int*   gt_classes    = (const int*)d_in[19];
    const int*   gt_attributes = (const int*)d_in[20];
    float* out = (float*)d_out;

    cudaFuncSetAttribute(k_meta, cudaFuncAttributeMaxDynamicSharedMemorySize,
                         49152 * (int)sizeof(float));  // 192 KB

    k_pre<<<345, 256>>>(class_embIn, class_embOut, attr_embIn, attr_embOut,   // 1
                        gt_classes, gt_attributes, axon_w1, concept_embOut,
                        program_args);
    k_meta<<<B_, 512, 49152 * sizeof(float)>>>(meta_init, meta_w1, meta_b1,   // 2
                                               meta_w2, meta_b2, program_ops);
    k_proj<<<dim3(N_ / 8, B_), 256>>>(concept_embOut, concept_embIn);         // 3
    k_D<<<dim3(N_ / 192, L_, B_), 256>>>(program_ops, concept_embIn,          // 4
                                         axon_w1, axon_b1);
    k_E<<<dim3(L_, B_), 256>>>(program_ops, axon_w2);                         // 5
    k_rec<<<B_, 1024>>>(program_ops, axon_b2, attention_init);                // 6
    k_final<<<dim3(N_ / 32, B_), dim3(16, 8)>>>(program_ops, concept_embIn,   // 7
                                                attention_init);
    k_soft<<<B_, 1024>>>(out);                                                // 8
}